// round 10
// baseline (speedup 1.0000x reference)
#include <cuda_runtime.h>
#include <cuda_fp16.h>
#include <cstdint>
#include <math.h>

#define Bc 2
#define Tc 2048
#define Sc 2048
#define Ec 1024
#define Hc 16
#define HDc 64
#define QSCALE 0.125f

// Scratch (__device__ globals; allocation-free)
__device__ float g_q[(size_t)Bc*Hc*Tc*HDc];   // [bh,t,d]
__device__ float g_k[(size_t)Bc*Hc*Sc*HDc];   // [bh,s,d]
__device__ float g_v[(size_t)Bc*Hc*Sc*HDc];   // [bh,s,d]
__device__ float g_o[(size_t)Bc*Tc*Ec];       // [b,t,h,d]  attn out pre-Wo
__device__ __half g_p[(size_t)Bc*Hc*Tc*Sc];   // [bh,t,s]   raw masked scores (256 MB, fp16)
__device__ float g_c[Bc*Hc*Tc];               // m + log(sum)

__device__ __forceinline__ uint32_t cvt_tf32(float f) {
    uint32_t r; asm("cvt.rna.tf32.f32 %0, %1;" : "=r"(r) : "f"(f)); return r;
}
__device__ __forceinline__ uint32_t smem_u32(const void* p) {
    uint32_t a;
    asm("{ .reg .u64 t; cvta.to.shared.u64 t, %1; cvt.u32.u64 %0, t; }" : "=r"(a) : "l"(p));
    return a;
}
__device__ __forceinline__ void mma_tf32(float c[4], const uint32_t a[4], const uint32_t b[2]) {
    asm volatile(
        "mma.sync.aligned.m16n8k8.row.col.f32.tf32.tf32.f32 "
        "{%0,%1,%2,%3}, {%4,%5,%6,%7}, {%8,%9}, {%0,%1,%2,%3};"
        : "+f"(c[0]), "+f"(c[1]), "+f"(c[2]), "+f"(c[3])
        : "r"(a[0]), "r"(a[1]), "r"(a[2]), "r"(a[3]), "r"(b[0]), "r"(b[1]));
}
__device__ __forceinline__ void mma_f16(float c[4], const uint32_t a[4], uint32_t b0, uint32_t b1) {
    asm volatile(
        "mma.sync.aligned.m16n8k16.row.col.f32.f16.f16.f32 "
        "{%0,%1,%2,%3}, {%4,%5,%6,%7}, {%8,%9}, {%0,%1,%2,%3};"
        : "+f"(c[0]), "+f"(c[1]), "+f"(c[2]), "+f"(c[3])
        : "r"(a[0]), "r"(a[1]), "r"(a[2]), "r"(a[3]), "r"(b0), "r"(b1));
}
__device__ __forceinline__ void ldsm4(uint32_t r[4], uint32_t addr) {
    asm volatile("ldmatrix.sync.aligned.m8n8.x4.shared.b16 {%0,%1,%2,%3}, [%4];"
        : "=r"(r[0]), "=r"(r[1]), "=r"(r[2]), "=r"(r[3]) : "r"(addr));
}
__device__ __forceinline__ void ldsm4t(uint32_t r[4], uint32_t addr) {
    asm volatile("ldmatrix.sync.aligned.m8n8.x4.trans.shared.b16 {%0,%1,%2,%3}, [%4];"
        : "=r"(r[0]), "=r"(r[1]), "=r"(r[2]), "=r"(r[3]) : "r"(addr));
}
__device__ __forceinline__ uint32_t pack_f16(float lo, float hi) {
    uint32_t r; asm("cvt.rn.f16x2.f32 %0, %1, %2;" : "=r"(r) : "f"(hi), "f"(lo)); return r;
}

// ---------------------------------------------------------------------------
// Double-buffered tf32 GEMM:  C = A[M,1024] @ W[1024,1024]^T (+bias)
// MODE 0: batched QKV projection (blockIdx.z selects q/k/v) -> g_q/g_k/g_v
// MODE 3: output projection (flat [row, col] out)
// ---------------------------------------------------------------------------
template<int MODE>
__global__ void __launch_bounds__(256, 2) gemm_db(
    const float* __restrict__ A0, const float* __restrict__ A1, const float* __restrict__ A2,
    const float* __restrict__ W0, const float* __restrict__ W1, const float* __restrict__ W2,
    const float* __restrict__ bias0, const float* __restrict__ bias1, const float* __restrict__ bias2,
    float* __restrict__ Cout)
{
    extern __shared__ uint32_t ds[];
    uint32_t* const Abuf[2] = { ds,         ds + 9216 };
    uint32_t* const Bbuf[2] = { ds + 4608,  ds + 13824 };

    const int tid  = threadIdx.x;
    const int wid  = tid >> 5;
    const int lane = tid & 31;
    const int wrow = wid >> 2;
    const int wcol = wid & 3;
    const int bm = blockIdx.y * 128;
    const int bn = blockIdx.x * 128;
    const int z  = blockIdx.z;

    const float* A; const float* W; const float* bias; float scale; float* dst;
    if (MODE == 0) {
        A    = (z == 0) ? A0 : (z == 1) ? A1 : A2;
        W    = (z == 0) ? W0 : (z == 1) ? W1 : W2;
        bias = (z == 0) ? bias0 : (z == 1) ? bias1 : bias2;
        scale = (z == 0) ? QSCALE : 1.0f;
        dst  = (z == 0) ? g_q : (z == 1) ? g_k : g_v;
    } else {
        A = A0; W = W0; bias = bias0; scale = 1.0f; dst = Cout;
    }

    float c[4][4][4];
    #pragma unroll
    for (int i = 0; i < 4; i++)
        #pragma unroll
        for (int j = 0; j < 4; j++)
            #pragma unroll
            for (int u = 0; u < 4; u++) c[i][j][u] = 0.f;

    const int aRow = wrow * 64 + (lane & 7) + ((lane >> 3) & 1) * 8;
    const int aCol = (lane >> 4) * 4;
    const int bRow = wcol * 32 + ((lane >> 4) * 8) + (lane & 7);
    const int bCol = ((lane >> 3) & 1) * 4;
    const uint32_t sA[2] = { smem_u32(Abuf[0]), smem_u32(Abuf[1]) };
    const uint32_t sB[2] = { smem_u32(Bbuf[0]), smem_u32(Bbuf[1]) };

    const int lrw = tid >> 3;
    const int lc4 = (tid & 7) * 4;

    float4 ra[4], rb[4];
    #pragma unroll
    for (int i = 0; i < 4; i++) {
        int row = lrw + i * 32;
        ra[i] = *(const float4*)(A + (size_t)(bm + row) * Ec + lc4);
        rb[i] = *(const float4*)(W + (size_t)(bn + row) * Ec + lc4);
    }
    #pragma unroll
    for (int i = 0; i < 4; i++) {
        int row = lrw + i * 32;
        *(uint4*)&Abuf[0][row * 36 + lc4] = make_uint4(cvt_tf32(ra[i].x), cvt_tf32(ra[i].y),
                                                       cvt_tf32(ra[i].z), cvt_tf32(ra[i].w));
        *(uint4*)&Bbuf[0][row * 36 + lc4] = make_uint4(cvt_tf32(rb[i].x), cvt_tf32(rb[i].y),
                                                       cvt_tf32(rb[i].z), cvt_tf32(rb[i].w));
    }
    __syncthreads();

    for (int ks = 0; ks < 32; ks++) {
        const int cur = ks & 1;
        if (ks < 31) {
            #pragma unroll
            for (int i = 0; i < 4; i++) {
                int row = lrw + i * 32;
                ra[i] = *(const float4*)(A + (size_t)(bm + row) * Ec + (ks + 1) * 32 + lc4);
                rb[i] = *(const float4*)(W + (size_t)(bn + row) * Ec + (ks + 1) * 32 + lc4);
            }
        }
        #pragma unroll
        for (int k8 = 0; k8 < 4; k8++) {
            uint32_t af[4][4], bf[4][2];
            #pragma unroll
            for (int mt = 0; mt < 4; mt++)
                ldsm4(af[mt], sA[cur] + (uint32_t)(((aRow + mt * 16) * 36 + k8 * 8 + aCol) * 4));
            #pragma unroll
            for (int np = 0; np < 2; np++) {
                uint32_t t4[4];
                ldsm4(t4, sB[cur] + (uint32_t)(((bRow + np * 16) * 36 + k8 * 8 + bCol) * 4));
                bf[2*np][0] = t4[0]; bf[2*np][1] = t4[1];
                bf[2*np+1][0] = t4[2]; bf[2*np+1][1] = t4[3];
            }
            #pragma unroll
            for (int mt = 0; mt < 4; mt++)
                #pragma unroll
                for (int nt = 0; nt < 4; nt++)
                    mma_tf32(c[mt][nt], af[mt], bf[nt]);
        }
        if (ks < 31) {
            #pragma unroll
            for (int i = 0; i < 4; i++) {
                int row = lrw + i * 32;
                *(uint4*)&Abuf[cur ^ 1][row * 36 + lc4] =
                    make_uint4(cvt_tf32(ra[i].x), cvt_tf32(ra[i].y), cvt_tf32(ra[i].z), cvt_tf32(ra[i].w));
                *(uint4*)&Bbuf[cur ^ 1][row * 36 + lc4] =
                    make_uint4(cvt_tf32(rb[i].x), cvt_tf32(rb[i].y), cvt_tf32(rb[i].z), cvt_tf32(rb[i].w));
            }
        }
        __syncthreads();
    }

    const int lrow = lane >> 2;
    const int lk   = lane & 3;
    #pragma unroll
    for (int mt = 0; mt < 4; mt++) {
        #pragma unroll
        for (int half = 0; half < 2; half++) {
            int row = bm + wrow * 64 + mt * 16 + lrow + half * 8;
            #pragma unroll
            for (int nt = 0; nt < 4; nt++) {
                int col = bn + wcol * 32 + nt * 8 + lk * 2;
                float v0 = c[mt][nt][half * 2];
                float v1 = c[mt][nt][half * 2 + 1];
                if (MODE == 0) {
                    int b = row >> 11, t = row & 2047;
                    int h = col >> 6, d = col & 63;
                    *(float2*)&dst[(((size_t)(b * Hc + h)) * Tc + t) * HDc + d] =
                        make_float2((v0 + bias[col]) * scale, (v1 + bias[col + 1]) * scale);
                } else {
                    *(float2*)&dst[(size_t)row * Ec + col] =
                        make_float2(v0 + bias[col], v1 + bias[col + 1]);
                }
            }
        }
    }
}

// ---------------------------------------------------------------------------
// attn_fused: per (bh, 64-row t-tile). Flash-style online softmax.
//   S = Q@K^T (tf32 mma, Q frags in regs), mask, raw S -> g_p (fp16),
//   online max/rescale, p = exp(S - m) packed fp16, O += P@V (fp16 mma).
// Writes g_o = O / sum and g_c = m + log(sum).
// ---------------------------------------------------------------------------
__global__ void __launch_bounds__(128, 3) attn_fused(
    const unsigned char* __restrict__ am, const unsigned char* __restrict__ kpm)
{
    __shared__ uint32_t Ks[64 * 68];   // Q staging, then K tiles (tf32)
    __shared__ uint32_t Vs[64 * 36];   // V tiles (fp16x2, 72-half row stride)

    const int tid  = threadIdx.x;
    const int w    = tid >> 5;
    const int lane = tid & 31;
    const int lrow = lane >> 2;
    const int lk   = lane & 3;
    const int tbase = blockIdx.x * 64;
    const int bh = blockIdx.y;
    const int b = bh >> 4, h = bh & 15;

    const float* Q  = g_q + (size_t)bh * Tc * HDc;
    const float* Kg = g_k + (size_t)bh * Sc * HDc;
    const float* Vg = g_v + (size_t)bh * Sc * HDc;

    const uint32_t sK = smem_u32(Ks);
    const uint32_t sV = smem_u32(Vs);

    // ---- stage Q tile (64x64) and load A-fragments into registers ----
    #pragma unroll
    for (int i = 0; i < 8; i++) {
        int flat = tid + i * 128;
        int row = flat >> 4, c4 = (flat & 15) * 4;
        float4 q = *(const float4*)(Q + (size_t)(tbase + row) * HDc + c4);
        *(uint4*)&Ks[row * 68 + c4] = make_uint4(cvt_tf32(q.x), cvt_tf32(q.y),
                                                 cvt_tf32(q.z), cvt_tf32(q.w));
    }
    __syncthreads();
    uint32_t aQ[8][4];
    const int aRow = w * 16 + (lane & 7) + ((lane >> 3) & 1) * 8;
    const int aCol = (lane >> 4) * 4;
    #pragma unroll
    for (int k8 = 0; k8 < 8; k8++)
        ldsm4(aQ[k8], sK + (uint32_t)((aRow * 68 + k8 * 8 + aCol) * 4));
    __syncthreads();

    float Oa[8][4];
    #pragma unroll
    for (int i = 0; i < 8; i++)
        #pragma unroll
        for (int u = 0; u < 4; u++) Oa[i][u] = 0.f;
    float m_lo = -1e30f, m_hi = -1e30f, s_lo = 0.f, s_hi = 0.f;

    const int t_lo = tbase + w * 16 + lrow;
    const int t_hi = t_lo + 8;

    for (int s0 = 0; s0 < Sc; s0 += 64) {
        // ---- load K (tf32) and V (fp16) tiles ----
        #pragma unroll
        for (int i = 0; i < 8; i++) {
            int flat = tid + i * 128;
            int row = flat >> 4, c4 = (flat & 15) * 4;
            float4 kv = *(const float4*)(Kg + (size_t)(s0 + row) * HDc + c4);
            *(uint4*)&Ks[row * 68 + c4] = make_uint4(cvt_tf32(kv.x), cvt_tf32(kv.y),
                                                     cvt_tf32(kv.z), cvt_tf32(kv.w));
            float4 vv = *(const float4*)(Vg + (size_t)(s0 + row) * HDc + c4);
            Vs[row * 36 + (c4 >> 1)]     = pack_f16(vv.x, vv.y);
            Vs[row * 36 + (c4 >> 1) + 1] = pack_f16(vv.z, vv.w);
        }
        __syncthreads();

        // ---- S = Q @ K^T ----
        float S[8][4];
        #pragma unroll
        for (int nt = 0; nt < 8; nt++)
            #pragma unroll
            for (int u = 0; u < 4; u++) S[nt][u] = 0.f;
        #pragma unroll
        for (int k8 = 0; k8 < 8; k8++) {
            uint32_t bf[8][2];
            #pragma unroll
            for (int np = 0; np < 4; np++) {
                uint32_t t4[4];
                int brow = np * 16 + ((lane >> 4) * 8) + (lane & 7);
                ldsm4(t4, sK + (uint32_t)((brow * 68 + k8 * 8 + ((lane >> 3) & 1) * 4) * 4));
                bf[2*np][0] = t4[0]; bf[2*np][1] = t4[1];
                bf[2*np+1][0] = t4[2]; bf[2*np+1][1] = t4[3];
            }
            #pragma unroll
            for (int nt = 0; nt < 8; nt++)
                mma_tf32(S[nt], aQ[k8], bf[nt]);
        }

        // ---- mask, raw-score write (fp16), tile max ----
        float tmax_lo = -1e30f, tmax_hi = -1e30f;
        #pragma unroll
        for (int nt = 0; nt < 8; nt++) {
            int col = s0 + nt * 8 + lk * 2;
            uchar2 a0 = *(const uchar2*)&am[(size_t)t_lo * Sc + col];
            uchar2 a1 = *(const uchar2*)&am[(size_t)t_hi * Sc + col];
            uchar2 kp = *(const uchar2*)&kpm[(size_t)b * Sc + col];
            if (a0.x | kp.x) S[nt][0] = 1e-10f;
            if (a0.y | kp.y) S[nt][1] = 1e-10f;
            if (a1.x | kp.x) S[nt][2] = 1e-10f;
            if (a1.y | kp.y) S[nt][3] = 1e-10f;
            *(uint32_t*)&g_p[((size_t)bh * Tc + t_lo) * Sc + col] = pack_f16(S[nt][0], S[nt][1]);
            *(uint32_t*)&g_p[((size_t)bh * Tc + t_hi) * Sc + col] = pack_f16(S[nt][2], S[nt][3]);
            tmax_lo = fmaxf(tmax_lo, fmaxf(S[nt][0], S[nt][1]));
            tmax_hi = fmaxf(tmax_hi, fmaxf(S[nt][2], S[nt][3]));
        }
        tmax_lo = fmaxf(tmax_lo, __shfl_xor_sync(0xffffffffu, tmax_lo, 1));
        tmax_lo = fmaxf(tmax_lo, __shfl_xor_sync(0xffffffffu, tmax_lo, 2));
        tmax_hi = fmaxf(tmax_hi, __shfl_xor_sync(0xffffffffu, tmax_hi, 1));
        tmax_hi = fmaxf(tmax_hi, __shfl_xor_sync(0xffffffffu, tmax_hi, 2));

        // ---- online rescale ----
        float mnew_lo = fmaxf(m_lo, tmax_lo);
        float mnew_hi = fmaxf(m_hi, tmax_hi);
        float f_lo = __expf(m_lo - mnew_lo);
        float f_hi = __expf(m_hi - mnew_hi);
        m_lo = mnew_lo; m_hi = mnew_hi;
        s_lo *= f_lo;   s_hi *= f_hi;
        #pragma unroll
        for (int nd = 0; nd < 8; nd++) {
            Oa[nd][0] *= f_lo; Oa[nd][1] *= f_lo;
            Oa[nd][2] *= f_hi; Oa[nd][3] *= f_hi;
        }

        // ---- p = exp(S - m), sums, fp16 pack ----
        uint32_t aP[4][4];
        #pragma unroll
        for (int nt = 0; nt < 8; nt++) {
            float p0 = __expf(S[nt][0] - m_lo);
            float p1 = __expf(S[nt][1] - m_lo);
            float p2 = __expf(S[nt][2] - m_hi);
            float p3 = __expf(S[nt][3] - m_hi);
            s_lo += p0 + p1;
            s_hi += p2 + p3;
            int kk = nt >> 1, hi = (nt & 1) * 2;
            aP[kk][hi]     = pack_f16(p0, p1);
            aP[kk][hi + 1] = pack_f16(p2, p3);
        }

        // ---- O += P @ V  (fp16 m16n8k16, B via ldmatrix.trans) ----
        #pragma unroll
        for (int kk = 0; kk < 4; kk++) {
            int vrow = kk * 16 + (lane & 7) + ((lane >> 3) & 1) * 8;
            #pragma unroll
            for (int nd16 = 0; nd16 < 4; nd16++) {
                uint32_t t4[4];
                int vcol = nd16 * 16 + (lane >> 4) * 8;
                ldsm4t(t4, sV + (uint32_t)((vrow * 72 + vcol) * 2));
                mma_f16(Oa[nd16 * 2],     aP[kk], t4[0], t4[1]);
                mma_f16(Oa[nd16 * 2 + 1], aP[kk], t4[2], t4[3]);
            }
        }
        __syncthreads();
    }

    // ---- epilogue ----
    float r_lo = s_lo, r_hi = s_hi;
    r_lo += __shfl_xor_sync(0xffffffffu, r_lo, 1);
    r_lo += __shfl_xor_sync(0xffffffffu, r_lo, 2);
    r_hi += __shfl_xor_sync(0xffffffffu, r_hi, 1);
    r_hi += __shfl_xor_sync(0xffffffffu, r_hi, 2);
    const float inv_lo = 1.0f / r_lo;
    const float inv_hi = 1.0f / r_hi;

    #pragma unroll
    for (int nd = 0; nd < 8; nd++) {
        int d = nd * 8 + lk * 2;
        *(float2*)&g_o[(((size_t)b * Tc + t_lo) * Hc + h) * HDc + d] =
            make_float2(Oa[nd][0] * inv_lo, Oa[nd][1] * inv_lo);
        *(float2*)&g_o[(((size_t)b * Tc + t_hi) * Hc + h) * HDc + d] =
            make_float2(Oa[nd][2] * inv_hi, Oa[nd][3] * inv_hi);
    }
    if (lk == 0) {
        g_c[(size_t)bh * Tc + t_lo] = m_lo + __logf(r_lo);
        g_c[(size_t)bh * Tc + t_hi] = m_hi + __logf(r_hi);
    }
}

// ---------------------------------------------------------------------------
// headmax: attn_max[b,t,s] = exp(max_h (score_f16[b,h,t,s] - c[b,h,t]))
// One block per (b,t); each thread covers 8 s-positions via half8 loads.
// ---------------------------------------------------------------------------
__global__ void __launch_bounds__(256) headmax_kernel(float* __restrict__ out2)
{
    size_t i8 = (size_t)blockIdx.x * 256 + threadIdx.x;   // over B*T*S/8
    size_t sq = i8 % (Sc / 8);
    size_t bt = i8 / (Sc / 8);
    size_t b = bt >> 11, t = bt & 2047;
    size_t s = sq * 8;

    float best[8];
    #pragma unroll
    for (int u = 0; u < 8; u++) best[u] = -1e30f;

    #pragma unroll
    for (int h = 0; h < Hc; h++) {
        size_t bh = b * Hc + h;
        float ch = g_c[bh * Tc + t];
        uint4 raw = *(const uint4*)&g_p[(bh * Tc + t) * Sc + s];
        float2 f0 = __half22float2(*(const __half2*)&raw.x);
        float2 f1 = __half22float2(*(const __half2*)&raw.y);
        float2 f2 = __half22float2(*(const __half2*)&raw.z);
        float2 f3 = __half22float2(*(const __half2*)&raw.w);
        best[0] = fmaxf(best[0], f0.x - ch); best[1] = fmaxf(best[1], f0.y - ch);
        best[2] = fmaxf(best[2], f1.x - ch); best[3] = fmaxf(best[3], f1.y - ch);
        best[4] = fmaxf(best[4], f2.x - ch); best[5] = fmaxf(best[5], f2.y - ch);
        best[6] = fmaxf(best[6], f3.x - ch); best[7] = fmaxf(best[7], f3.y - ch);
    }
    float* dst = &out2[bt * Sc + s];
    *(float4*)dst       = make_float4(__expf(best[0]), __expf(best[1]),
                                      __expf(best[2]), __expf(best[3]));
    *(float4*)(dst + 4) = make_float4(__expf(best[4]), __expf(best[5]),
                                      __expf(best[6]), __expf(best[7]));
}

// ---------------------------------------------------------------------------
extern "C" void kernel_launch(void* const* d_in, const int* in_sizes, int n_in,
                              void* d_out, int out_size)
{
    const float* query = (const float*)d_in[0];
    const float* key   = (const float*)d_in[1];
    const float* value = (const float*)d_in[2];
    const unsigned char* kpm = (const unsigned char*)d_in[3];
    const unsigned char* am  = (const unsigned char*)d_in[4];
    const float* Wq = (const float*)d_in[5];
    const float* bq = (const float*)d_in[6];
    const float* Wk = (const float*)d_in[7];
    const float* bk = (const float*)d_in[8];
    const float* Wv = (const float*)d_in[9];
    const float* bv = (const float*)d_in[10];
    const float* Wo = (const float*)d_in[11];
    const float* bo = (const float*)d_in[12];

    float* out      = (float*)d_out;
    float* attn_max = (float*)d_out + (size_t)Bc * Tc * Ec;

    float *po;
    cudaGetSymbolAddress((void**)&po, g_o);

    const int GEMM_SMEM = 4 * 128 * 36 * 4;   // 73728 (double buffer)
    cudaFuncSetAttribute(gemm_db<0>, cudaFuncAttributeMaxDynamicSharedMemorySize, GEMM_SMEM);
    cudaFuncSetAttribute(gemm_db<3>, cudaFuncAttributeMaxDynamicSharedMemorySize, GEMM_SMEM);

    dim3 thr(256);

    // Batched Q/K/V projections (grid.z = 0,1,2)
    gemm_db<0><<<dim3(Ec / 128, (Bc * Tc) / 128, 3), thr, GEMM_SMEM>>>(
        query, key, value, Wq, Wk, Wv, bq, bk, bv, nullptr);

    // Fused score + online softmax + P@V  (fp16 raw scores -> g_p, stats -> g_c)
    attn_fused<<<dim3(Tc / 64, Bc * Hc), dim3(128)>>>(am, kpm);

    // attn_max output
    headmax_kernel<<<dim3((unsigned)(((size_t)Bc * Tc * Sc / 8) / 256)), thr>>>(attn_max);

    // Output projection
    gemm_db<3><<<dim3(Ec / 128, (Bc * Tc) / 128, 1), thr, GEMM_SMEM>>>(
        po, nullptr, nullptr, Wo, nullptr, nullptr, bo, nullptr, nullptr, out);
}

// round 11
// speedup vs baseline: 1.2623x; 1.2623x over previous
#include <cuda_runtime.h>
#include <cstdint>
#include <math.h>

#define Bc 2
#define Tc 2048
#define Sc 2048
#define Ec 1024
#define Hc 16
#define HDc 64
#define QSCALE 0.125f

// Scratch (__device__ globals; allocation-free)
__device__ float g_q[(size_t)Bc*Hc*Tc*HDc];   // [bh,t,d]
__device__ float g_k[(size_t)Bc*Hc*Sc*HDc];   // [bh,s,d]
__device__ float g_v[(size_t)Bc*Hc*Sc*HDc];   // [bh,s,d]
__device__ float g_o[(size_t)Bc*Tc*Ec];       // [b,t,h,d]  attn out pre-Wo
__device__ float g_p[(size_t)Bc*Hc*Tc*Sc];    // [bh,t,s]   raw masked scores (512 MB)
__device__ float g_c[Bc*Hc*Tc];               // m + log(sum)

__device__ __forceinline__ uint32_t cvt_tf32(float f) {
    uint32_t r; asm("cvt.rna.tf32.f32 %0, %1;" : "=r"(r) : "f"(f)); return r;
}
__device__ __forceinline__ uint32_t smem_u32(const void* p) {
    uint32_t a;
    asm("{ .reg .u64 t; cvta.to.shared.u64 t, %1; cvt.u32.u64 %0, t; }" : "=r"(a) : "l"(p));
    return a;
}
__device__ __forceinline__ void mma_tf32(float c[4], const uint32_t a[4], const uint32_t b[2]) {
    asm volatile(
        "mma.sync.aligned.m16n8k8.row.col.f32.tf32.tf32.f32 "
        "{%0,%1,%2,%3}, {%4,%5,%6,%7}, {%8,%9}, {%0,%1,%2,%3};"
        : "+f"(c[0]), "+f"(c[1]), "+f"(c[2]), "+f"(c[3])
        : "r"(a[0]), "r"(a[1]), "r"(a[2]), "r"(a[3]), "r"(b[0]), "r"(b[1]));
}
__device__ __forceinline__ void mma_f16(float c[4], const uint32_t a[4], uint32_t b0, uint32_t b1) {
    asm volatile(
        "mma.sync.aligned.m16n8k16.row.col.f32.f16.f16.f32 "
        "{%0,%1,%2,%3}, {%4,%5,%6,%7}, {%8,%9}, {%0,%1,%2,%3};"
        : "+f"(c[0]), "+f"(c[1]), "+f"(c[2]), "+f"(c[3])
        : "r"(a[0]), "r"(a[1]), "r"(a[2]), "r"(a[3]), "r"(b0), "r"(b1));
}
__device__ __forceinline__ void ldsm4(uint32_t r[4], uint32_t addr) {
    asm volatile("ldmatrix.sync.aligned.m8n8.x4.shared.b16 {%0,%1,%2,%3}, [%4];"
        : "=r"(r[0]), "=r"(r[1]), "=r"(r[2]), "=r"(r[3]) : "r"(addr));
}
__device__ __forceinline__ void ldsm4t(uint32_t r[4], uint32_t addr) {
    asm volatile("ldmatrix.sync.aligned.m8n8.x4.trans.shared.b16 {%0,%1,%2,%3}, [%4];"
        : "=r"(r[0]), "=r"(r[1]), "=r"(r[2]), "=r"(r[3]) : "r"(addr));
}
__device__ __forceinline__ uint32_t pack_f16(float lo, float hi) {
    uint32_t r; asm("cvt.rn.f16x2.f32 %0, %1, %2;" : "=r"(r) : "f"(hi), "f"(lo)); return r;
}

// ---------------------------------------------------------------------------
// Double-buffered tf32 GEMM:  C = A[M,1024] @ W[1024,1024]^T (+bias)
// MODE 0: batched QKV projection (blockIdx.z selects q/k/v) -> g_q/g_k/g_v
// MODE 3: output projection (flat [row, col] out)
// ---------------------------------------------------------------------------
template<int MODE>
__global__ void __launch_bounds__(256, 2) gemm_db(
    const float* __restrict__ A0, const float* __restrict__ A1, const float* __restrict__ A2,
    const float* __restrict__ W0, const float* __restrict__ W1, const float* __restrict__ W2,
    const float* __restrict__ bias0, const float* __restrict__ bias1, const float* __restrict__ bias2,
    float* __restrict__ Cout)
{
    extern __shared__ uint32_t ds[];
    uint32_t* const Abuf[2] = { ds,         ds + 9216 };
    uint32_t* const Bbuf[2] = { ds + 4608,  ds + 13824 };

    const int tid  = threadIdx.x;
    const int wid  = tid >> 5;
    const int lane = tid & 31;
    const int wrow = wid >> 2;
    const int wcol = wid & 3;
    const int bm = blockIdx.y * 128;
    const int bn = blockIdx.x * 128;
    const int z  = blockIdx.z;

    const float* A; const float* W; const float* bias; float scale; float* dst;
    if (MODE == 0) {
        A    = (z == 0) ? A0 : (z == 1) ? A1 : A2;
        W    = (z == 0) ? W0 : (z == 1) ? W1 : W2;
        bias = (z == 0) ? bias0 : (z == 1) ? bias1 : bias2;
        scale = (z == 0) ? QSCALE : 1.0f;
        dst  = (z == 0) ? g_q : (z == 1) ? g_k : g_v;
    } else {
        A = A0; W = W0; bias = bias0; scale = 1.0f; dst = Cout;
    }

    float c[4][4][4];
    #pragma unroll
    for (int i = 0; i < 4; i++)
        #pragma unroll
        for (int j = 0; j < 4; j++)
            #pragma unroll
            for (int u = 0; u < 4; u++) c[i][j][u] = 0.f;

    const int aRow = wrow * 64 + (lane & 7) + ((lane >> 3) & 1) * 8;
    const int aCol = (lane >> 4) * 4;
    const int bRow = wcol * 32 + ((lane >> 4) * 8) + (lane & 7);
    const int bCol = ((lane >> 3) & 1) * 4;
    const uint32_t sA[2] = { smem_u32(Abuf[0]), smem_u32(Abuf[1]) };
    const uint32_t sB[2] = { smem_u32(Bbuf[0]), smem_u32(Bbuf[1]) };

    const int lrw = tid >> 3;
    const int lc4 = (tid & 7) * 4;

    float4 ra[4], rb[4];
    #pragma unroll
    for (int i = 0; i < 4; i++) {
        int row = lrw + i * 32;
        ra[i] = *(const float4*)(A + (size_t)(bm + row) * Ec + lc4);
        rb[i] = *(const float4*)(W + (size_t)(bn + row) * Ec + lc4);
    }
    #pragma unroll
    for (int i = 0; i < 4; i++) {
        int row = lrw + i * 32;
        *(uint4*)&Abuf[0][row * 36 + lc4] = make_uint4(cvt_tf32(ra[i].x), cvt_tf32(ra[i].y),
                                                       cvt_tf32(ra[i].z), cvt_tf32(ra[i].w));
        *(uint4*)&Bbuf[0][row * 36 + lc4] = make_uint4(cvt_tf32(rb[i].x), cvt_tf32(rb[i].y),
                                                       cvt_tf32(rb[i].z), cvt_tf32(rb[i].w));
    }
    __syncthreads();

    for (int ks = 0; ks < 32; ks++) {
        const int cur = ks & 1;
        if (ks < 31) {
            #pragma unroll
            for (int i = 0; i < 4; i++) {
                int row = lrw + i * 32;
                ra[i] = *(const float4*)(A + (size_t)(bm + row) * Ec + (ks + 1) * 32 + lc4);
                rb[i] = *(const float4*)(W + (size_t)(bn + row) * Ec + (ks + 1) * 32 + lc4);
            }
        }
        #pragma unroll
        for (int k8 = 0; k8 < 4; k8++) {
            uint32_t af[4][4], bf[4][2];
            #pragma unroll
            for (int mt = 0; mt < 4; mt++)
                ldsm4(af[mt], sA[cur] + (uint32_t)(((aRow + mt * 16) * 36 + k8 * 8 + aCol) * 4));
            #pragma unroll
            for (int np = 0; np < 2; np++) {
                uint32_t t4[4];
                ldsm4(t4, sB[cur] + (uint32_t)(((bRow + np * 16) * 36 + k8 * 8 + bCol) * 4));
                bf[2*np][0] = t4[0]; bf[2*np][1] = t4[1];
                bf[2*np+1][0] = t4[2]; bf[2*np+1][1] = t4[3];
            }
            #pragma unroll
            for (int mt = 0; mt < 4; mt++)
                #pragma unroll
                for (int nt = 0; nt < 4; nt++)
                    mma_tf32(c[mt][nt], af[mt], bf[nt]);
        }
        if (ks < 31) {
            #pragma unroll
            for (int i = 0; i < 4; i++) {
                int row = lrw + i * 32;
                *(uint4*)&Abuf[cur ^ 1][row * 36 + lc4] =
                    make_uint4(cvt_tf32(ra[i].x), cvt_tf32(ra[i].y), cvt_tf32(ra[i].z), cvt_tf32(ra[i].w));
                *(uint4*)&Bbuf[cur ^ 1][row * 36 + lc4] =
                    make_uint4(cvt_tf32(rb[i].x), cvt_tf32(rb[i].y), cvt_tf32(rb[i].z), cvt_tf32(rb[i].w));
            }
        }
        __syncthreads();
    }

    const int lrow = lane >> 2;
    const int lk   = lane & 3;
    #pragma unroll
    for (int mt = 0; mt < 4; mt++) {
        #pragma unroll
        for (int half = 0; half < 2; half++) {
            int row = bm + wrow * 64 + mt * 16 + lrow + half * 8;
            #pragma unroll
            for (int nt = 0; nt < 4; nt++) {
                int col = bn + wcol * 32 + nt * 8 + lk * 2;
                float v0 = c[mt][nt][half * 2];
                float v1 = c[mt][nt][half * 2 + 1];
                if (MODE == 0) {
                    int b = row >> 11, t = row & 2047;
                    int h = col >> 6, d = col & 63;
                    *(float2*)&dst[(((size_t)(b * Hc + h)) * Tc + t) * HDc + d] =
                        make_float2((v0 + bias[col]) * scale, (v1 + bias[col + 1]) * scale);
                } else {
                    *(float2*)&dst[(size_t)row * Ec + col] =
                        make_float2(v0 + bias[col], v1 + bias[col + 1]);
                }
            }
        }
    }
}

// ---------------------------------------------------------------------------
// attn_fused: per (bh, 64-row t-tile). Flash-style online softmax.
//   S = Q@K^T (tf32 mma, Q frags in regs), mask, raw S -> g_p,
//   online max/rescale, p = exp(S - m) packed fp16, O += P@V (fp16 mma).
// Writes g_o = O / sum and g_c = m + log(sum).
// ---------------------------------------------------------------------------
__global__ void __launch_bounds__(128, 3) attn_fused(
    const unsigned char* __restrict__ am, const unsigned char* __restrict__ kpm)
{
    __shared__ uint32_t Ks[64 * 68];   // Q staging, then K tiles (tf32)
    __shared__ uint32_t Vs[64 * 36];   // V tiles (fp16x2, 72-half row stride)

    const int tid  = threadIdx.x;
    const int w    = tid >> 5;
    const int lane = tid & 31;
    const int lrow = lane >> 2;
    const int lk   = lane & 3;
    const int tbase = blockIdx.x * 64;
    const int bh = blockIdx.y;
    const int b = bh >> 4, h = bh & 15;

    const float* Q  = g_q + (size_t)bh * Tc * HDc;
    const float* Kg = g_k + (size_t)bh * Sc * HDc;
    const float* Vg = g_v + (size_t)bh * Sc * HDc;

    const uint32_t sK = smem_u32(Ks);
    const uint32_t sV = smem_u32(Vs);

    // ---- stage Q tile (64x64) and load A-fragments into registers ----
    #pragma unroll
    for (int i = 0; i < 8; i++) {
        int flat = tid + i * 128;
        int row = flat >> 4, c4 = (flat & 15) * 4;
        float4 q = *(const float4*)(Q + (size_t)(tbase + row) * HDc + c4);
        *(uint4*)&Ks[row * 68 + c4] = make_uint4(cvt_tf32(q.x), cvt_tf32(q.y),
                                                 cvt_tf32(q.z), cvt_tf32(q.w));
    }
    __syncthreads();
    uint32_t aQ[8][4];
    const int aRow = w * 16 + (lane & 7) + ((lane >> 3) & 1) * 8;
    const int aCol = (lane >> 4) * 4;
    #pragma unroll
    for (int k8 = 0; k8 < 8; k8++)
        ldsm4(aQ[k8], sK + (uint32_t)((aRow * 68 + k8 * 8 + aCol) * 4));
    __syncthreads();

    float Oa[8][4];
    #pragma unroll
    for (int i = 0; i < 8; i++)
        #pragma unroll
        for (int u = 0; u < 4; u++) Oa[i][u] = 0.f;
    float m_lo = -1e30f, m_hi = -1e30f, s_lo = 0.f, s_hi = 0.f;

    const int t_lo = tbase + w * 16 + lrow;
    const int t_hi = t_lo + 8;

    for (int s0 = 0; s0 < Sc; s0 += 64) {
        // ---- load K (tf32) and V (fp16) tiles ----
        #pragma unroll
        for (int i = 0; i < 8; i++) {
            int flat = tid + i * 128;
            int row = flat >> 4, c4 = (flat & 15) * 4;
            float4 kv = *(const float4*)(Kg + (size_t)(s0 + row) * HDc + c4);
            *(uint4*)&Ks[row * 68 + c4] = make_uint4(cvt_tf32(kv.x), cvt_tf32(kv.y),
                                                     cvt_tf32(kv.z), cvt_tf32(kv.w));
            float4 vv = *(const float4*)(Vg + (size_t)(s0 + row) * HDc + c4);
            Vs[row * 36 + (c4 >> 1)]     = pack_f16(vv.x, vv.y);
            Vs[row * 36 + (c4 >> 1) + 1] = pack_f16(vv.z, vv.w);
        }
        __syncthreads();

        // ---- S = Q @ K^T ----
        float S[8][4];
        #pragma unroll
        for (int nt = 0; nt < 8; nt++)
            #pragma unroll
            for (int u = 0; u < 4; u++) S[nt][u] = 0.f;
        #pragma unroll
        for (int k8 = 0; k8 < 8; k8++) {
            uint32_t bf[8][2];
            #pragma unroll
            for (int np = 0; np < 4; np++) {
                uint32_t t4[4];
                int brow = np * 16 + ((lane >> 4) * 8) + (lane & 7);
                ldsm4(t4, sK + (uint32_t)((brow * 68 + k8 * 8 + ((lane >> 3) & 1) * 4) * 4));
                bf[2*np][0] = t4[0]; bf[2*np][1] = t4[1];
                bf[2*np+1][0] = t4[2]; bf[2*np+1][1] = t4[3];
            }
            #pragma unroll
            for (int nt = 0; nt < 8; nt++)
                mma_tf32(S[nt], aQ[k8], bf[nt]);
        }

        // ---- mask, raw-score write, tile max ----
        float tmax_lo = -1e30f, tmax_hi = -1e30f;
        #pragma unroll
        for (int nt = 0; nt < 8; nt++) {
            int col = s0 + nt * 8 + lk * 2;
            uchar2 a0 = *(const uchar2*)&am[(size_t)t_lo * Sc + col];
            uchar2 a1 = *(const uchar2*)&am[(size_t)t_hi * Sc + col];
            uchar2 kp = *(const uchar2*)&kpm[(size_t)b * Sc + col];
            if (a0.x | kp.x) S[nt][0] = 1e-10f;
            if (a0.y | kp.y) S[nt][1] = 1e-10f;
            if (a1.x | kp.x) S[nt][2] = 1e-10f;
            if (a1.y | kp.y) S[nt][3] = 1e-10f;
            *(float2*)&g_p[((size_t)bh * Tc + t_lo) * Sc + col] = make_float2(S[nt][0], S[nt][1]);
            *(float2*)&g_p[((size_t)bh * Tc + t_hi) * Sc + col] = make_float2(S[nt][2], S[nt][3]);
            tmax_lo = fmaxf(tmax_lo, fmaxf(S[nt][0], S[nt][1]));
            tmax_hi = fmaxf(tmax_hi, fmaxf(S[nt][2], S[nt][3]));
        }
        tmax_lo = fmaxf(tmax_lo, __shfl_xor_sync(0xffffffffu, tmax_lo, 1));
        tmax_lo = fmaxf(tmax_lo, __shfl_xor_sync(0xffffffffu, tmax_lo, 2));
        tmax_hi = fmaxf(tmax_hi, __shfl_xor_sync(0xffffffffu, tmax_hi, 1));
        tmax_hi = fmaxf(tmax_hi, __shfl_xor_sync(0xffffffffu, tmax_hi, 2));

        // ---- online rescale ----
        float mnew_lo = fmaxf(m_lo, tmax_lo);
        float mnew_hi = fmaxf(m_hi, tmax_hi);
        float f_lo = __expf(m_lo - mnew_lo);
        float f_hi = __expf(m_hi - mnew_hi);
        m_lo = mnew_lo; m_hi = mnew_hi;
        s_lo *= f_lo;   s_hi *= f_hi;
        #pragma unroll
        for (int nd = 0; nd < 8; nd++) {
            Oa[nd][0] *= f_lo; Oa[nd][1] *= f_lo;
            Oa[nd][2] *= f_hi; Oa[nd][3] *= f_hi;
        }

        // ---- p = exp(S - m), sums, fp16 pack ----
        uint32_t aP[4][4];
        #pragma unroll
        for (int nt = 0; nt < 8; nt++) {
            float p0 = __expf(S[nt][0] - m_lo);
            float p1 = __expf(S[nt][1] - m_lo);
            float p2 = __expf(S[nt][2] - m_hi);
            float p3 = __expf(S[nt][3] - m_hi);
            s_lo += p0 + p1;
            s_hi += p2 + p3;
            int kk = nt >> 1, hi = (nt & 1) * 2;
            aP[kk][hi]     = pack_f16(p0, p1);
            aP[kk][hi + 1] = pack_f16(p2, p3);
        }

        // ---- O += P @ V  (fp16 m16n8k16, B via ldmatrix.trans) ----
        #pragma unroll
        for (int kk = 0; kk < 4; kk++) {
            int vrow = kk * 16 + (lane & 7) + ((lane >> 3) & 1) * 8;
            #pragma unroll
            for (int nd16 = 0; nd16 < 4; nd16++) {
                uint32_t t4[4];
                int vcol = nd16 * 16 + (lane >> 4) * 8;
                ldsm4t(t4, sV + (uint32_t)((vrow * 72 + vcol) * 2));
                mma_f16(Oa[nd16 * 2],     aP[kk], t4[0], t4[1]);
                mma_f16(Oa[nd16 * 2 + 1], aP[kk], t4[2], t4[3]);
            }
        }
        __syncthreads();
    }

    // ---- epilogue ----
    float r_lo = s_lo, r_hi = s_hi;
    r_lo += __shfl_xor_sync(0xffffffffu, r_lo, 1);
    r_lo += __shfl_xor_sync(0xffffffffu, r_lo, 2);
    r_hi += __shfl_xor_sync(0xffffffffu, r_hi, 1);
    r_hi += __shfl_xor_sync(0xffffffffu, r_hi, 2);
    const float inv_lo = 1.0f / r_lo;
    const float inv_hi = 1.0f / r_hi;

    #pragma unroll
    for (int nd = 0; nd < 8; nd++) {
        int d = nd * 8 + lk * 2;
        *(float2*)&g_o[(((size_t)b * Tc + t_lo) * Hc + h) * HDc + d] =
            make_float2(Oa[nd][0] * inv_lo, Oa[nd][1] * inv_lo);
        *(float2*)&g_o[(((size_t)b * Tc + t_hi) * Hc + h) * HDc + d] =
            make_float2(Oa[nd][2] * inv_hi, Oa[nd][3] * inv_hi);
    }
    if (lk == 0) {
        g_c[(size_t)bh * Tc + t_lo] = m_lo + __logf(r_lo);
        g_c[(size_t)bh * Tc + t_hi] = m_hi + __logf(r_hi);
    }
}

// ---------------------------------------------------------------------------
// headmax: attn_max[b,t,s] = exp(max_h (score[b,h,t,s] - c[b,h,t]))
// ---------------------------------------------------------------------------
__global__ void __launch_bounds__(256) headmax_kernel(float* __restrict__ out2)
{
    size_t i4 = (size_t)blockIdx.x * 256 + threadIdx.x;
    size_t sq = i4 % (Sc / 4);
    size_t bt = i4 / (Sc / 4);
    size_t b = bt >> 11, t = bt & 2047;
    size_t s = sq * 4;

    float4 best = make_float4(-1e30f, -1e30f, -1e30f, -1e30f);
    #pragma unroll
    for (int h = 0; h < Hc; h++) {
        size_t bh = b * Hc + h;
        float ch = g_c[bh * Tc + t];
        float4 sc = *(const float4*)&g_p[(bh * Tc + t) * Sc + s];
        best.x = fmaxf(best.x, sc.x - ch);
        best.y = fmaxf(best.y, sc.y - ch);
        best.z = fmaxf(best.z, sc.z - ch);
        best.w = fmaxf(best.w, sc.w - ch);
    }
    *(float4*)&out2[bt * Sc + s] =
        make_float4(__expf(best.x), __expf(best.y), __expf(best.z), __expf(best.w));
}

// ---------------------------------------------------------------------------
extern "C" void kernel_launch(void* const* d_in, const int* in_sizes, int n_in,
                              void* d_out, int out_size)
{
    const float* query = (const float*)d_in[0];
    const float* key   = (const float*)d_in[1];
    const float* value = (const float*)d_in[2];
    const unsigned char* kpm = (const unsigned char*)d_in[3];
    const unsigned char* am  = (const unsigned char*)d_in[4];
    const float* Wq = (const float*)d_in[5];
    const float* bq = (const float*)d_in[6];
    const float* Wk = (const float*)d_in[7];
    const float* bk = (const float*)d_in[8];
    const float* Wv = (const float*)d_in[9];
    const float* bv = (const float*)d_in[10];
    const float* Wo = (const float*)d_in[11];
    const float* bo = (const float*)d_in[12];

    float* out      = (float*)d_out;
    float* attn_max = (float*)d_out + (size_t)Bc * Tc * Ec;

    float *po;
    cudaGetSymbolAddress((void**)&po, g_o);

    // side stream + events for headmax || out-projection overlap (created once,
    // on the uncaptured correctness call; replayed identically afterwards)
    static cudaStream_t s2 = nullptr;
    static cudaEvent_t evFork = nullptr, evJoin = nullptr;
    if (s2 == nullptr) {
        cudaStreamCreateWithFlags(&s2, cudaStreamNonBlocking);
        cudaEventCreateWithFlags(&evFork, cudaEventDisableTiming);
        cudaEventCreateWithFlags(&evJoin, cudaEventDisableTiming);
    }

    const int GEMM_SMEM = 4 * 128 * 36 * 4;   // 73728 (double buffer)
    cudaFuncSetAttribute(gemm_db<0>, cudaFuncAttributeMaxDynamicSharedMemorySize, GEMM_SMEM);
    cudaFuncSetAttribute(gemm_db<3>, cudaFuncAttributeMaxDynamicSharedMemorySize, GEMM_SMEM);

    dim3 thr(256);

    // Batched Q/K/V projections (grid.z = 0,1,2)
    gemm_db<0><<<dim3(Ec / 128, (Bc * Tc) / 128, 3), thr, GEMM_SMEM>>>(
        query, key, value, Wq, Wk, Wv, bq, bk, bv, nullptr);

    // Fused score + online softmax + P@V  (raw scores -> g_p, stats -> g_c)
    attn_fused<<<dim3(Tc / 64, Bc * Hc), dim3(128)>>>(am, kpm);

    // fork: headmax on side stream, out-projection on main stream, then join
    cudaEventRecord(evFork, 0);
    cudaStreamWaitEvent(s2, evFork, 0);

    headmax_kernel<<<dim3((unsigned)(((size_t)Bc * Tc * Sc / 4) / 256)), thr, 0, s2>>>(attn_max);

    gemm_db<3><<<dim3(Ec / 128, (Bc * Tc) / 128, 1), thr, GEMM_SMEM>>>(
        po, nullptr, nullptr, Wo, nullptr, nullptr, bo, nullptr, nullptr, out);

    cudaEventRecord(evJoin, s2);
    cudaStreamWaitEvent(0, evJoin, 0);
}

// round 12
// speedup vs baseline: 1.6080x; 1.2738x over previous
#include <cuda_runtime.h>
#include <cuda_fp16.h>
#include <cstdint>
#include <math.h>

#define Bc 2
#define Tc 2048
#define Sc 2048
#define Ec 1024
#define Hc 16
#define HDc 64
#define QSCALE 0.125f

// Scratch (__device__ globals; allocation-free)
__device__ __half g_q[(size_t)Bc*Hc*Tc*HDc];  // [bh,t,d] fp16
__device__ __half g_k[(size_t)Bc*Hc*Sc*HDc];  // [bh,s,d] fp16
__device__ __half g_v[(size_t)Bc*Hc*Sc*HDc];  // [bh,s,d] fp16
__device__ float  g_o[(size_t)Bc*Tc*Ec];      // [b,t,h,d]  attn out pre-Wo
__device__ float  g_p[(size_t)Bc*Hc*Tc*Sc];   // [bh,t,s]   raw masked scores (512 MB)
__device__ float  g_c[Bc*Hc*Tc];              // m + log(sum)

__device__ __forceinline__ uint32_t cvt_tf32(float f) {
    uint32_t r; asm("cvt.rna.tf32.f32 %0, %1;" : "=r"(r) : "f"(f)); return r;
}
__device__ __forceinline__ uint32_t smem_u32(const void* p) {
    uint32_t a;
    asm("{ .reg .u64 t; cvta.to.shared.u64 t, %1; cvt.u32.u64 %0, t; }" : "=r"(a) : "l"(p));
    return a;
}
__device__ __forceinline__ void mma_tf32(float c[4], const uint32_t a[4], const uint32_t b[2]) {
    asm volatile(
        "mma.sync.aligned.m16n8k8.row.col.f32.tf32.tf32.f32 "
        "{%0,%1,%2,%3}, {%4,%5,%6,%7}, {%8,%9}, {%0,%1,%2,%3};"
        : "+f"(c[0]), "+f"(c[1]), "+f"(c[2]), "+f"(c[3])
        : "r"(a[0]), "r"(a[1]), "r"(a[2]), "r"(a[3]), "r"(b[0]), "r"(b[1]));
}
__device__ __forceinline__ void mma_f16(float c[4], const uint32_t a[4], uint32_t b0, uint32_t b1) {
    asm volatile(
        "mma.sync.aligned.m16n8k16.row.col.f32.f16.f16.f32 "
        "{%0,%1,%2,%3}, {%4,%5,%6,%7}, {%8,%9}, {%0,%1,%2,%3};"
        : "+f"(c[0]), "+f"(c[1]), "+f"(c[2]), "+f"(c[3])
        : "r"(a[0]), "r"(a[1]), "r"(a[2]), "r"(a[3]), "r"(b0), "r"(b1));
}
__device__ __forceinline__ void ldsm4(uint32_t r[4], uint32_t addr) {
    asm volatile("ldmatrix.sync.aligned.m8n8.x4.shared.b16 {%0,%1,%2,%3}, [%4];"
        : "=r"(r[0]), "=r"(r[1]), "=r"(r[2]), "=r"(r[3]) : "r"(addr));
}
__device__ __forceinline__ void ldsm4t(uint32_t r[4], uint32_t addr) {
    asm volatile("ldmatrix.sync.aligned.m8n8.x4.trans.shared.b16 {%0,%1,%2,%3}, [%4];"
        : "=r"(r[0]), "=r"(r[1]), "=r"(r[2]), "=r"(r[3]) : "r"(addr));
}
__device__ __forceinline__ uint32_t pack_f16(float lo, float hi) {
    uint32_t r; asm("cvt.rn.f16x2.f32 %0, %1, %2;" : "=r"(r) : "f"(hi), "f"(lo)); return r;
}

// ---------------------------------------------------------------------------
// Double-buffered tf32 GEMM:  C = A[M,1024] @ W[1024,1024]^T (+bias)
// MODE 0: batched QKV projection (blockIdx.z selects q/k/v) -> fp16 g_q/g_k/g_v
// MODE 3: output projection (flat fp32 [row, col] out)
// ---------------------------------------------------------------------------
template<int MODE>
__global__ void __launch_bounds__(256, 2) gemm_db(
    const float* __restrict__ A0, const float* __restrict__ A1, const float* __restrict__ A2,
    const float* __restrict__ W0, const float* __restrict__ W1, const float* __restrict__ W2,
    const float* __restrict__ bias0, const float* __restrict__ bias1, const float* __restrict__ bias2,
    float* __restrict__ Cout)
{
    extern __shared__ uint32_t ds[];
    uint32_t* const Abuf[2] = { ds,         ds + 9216 };
    uint32_t* const Bbuf[2] = { ds + 4608,  ds + 13824 };

    const int tid  = threadIdx.x;
    const int wid  = tid >> 5;
    const int lane = tid & 31;
    const int wrow = wid >> 2;
    const int wcol = wid & 3;
    const int bm = blockIdx.y * 128;
    const int bn = blockIdx.x * 128;
    const int z  = blockIdx.z;

    const float* A; const float* W; const float* bias; float scale;
    __half* hdst = nullptr;
    if (MODE == 0) {
        A    = (z == 0) ? A0 : (z == 1) ? A1 : A2;
        W    = (z == 0) ? W0 : (z == 1) ? W1 : W2;
        bias = (z == 0) ? bias0 : (z == 1) ? bias1 : bias2;
        scale = (z == 0) ? QSCALE : 1.0f;
        hdst = (z == 0) ? g_q : (z == 1) ? g_k : g_v;
    } else {
        A = A0; W = W0; bias = bias0; scale = 1.0f;
    }

    float c[4][4][4];
    #pragma unroll
    for (int i = 0; i < 4; i++)
        #pragma unroll
        for (int j = 0; j < 4; j++)
            #pragma unroll
            for (int u = 0; u < 4; u++) c[i][j][u] = 0.f;

    const int aRow = wrow * 64 + (lane & 7) + ((lane >> 3) & 1) * 8;
    const int aCol = (lane >> 4) * 4;
    const int bRow = wcol * 32 + ((lane >> 4) * 8) + (lane & 7);
    const int bCol = ((lane >> 3) & 1) * 4;
    const uint32_t sA[2] = { smem_u32(Abuf[0]), smem_u32(Abuf[1]) };
    const uint32_t sB[2] = { smem_u32(Bbuf[0]), smem_u32(Bbuf[1]) };

    const int lrw = tid >> 3;
    const int lc4 = (tid & 7) * 4;

    float4 ra[4], rb[4];
    #pragma unroll
    for (int i = 0; i < 4; i++) {
        int row = lrw + i * 32;
        ra[i] = *(const float4*)(A + (size_t)(bm + row) * Ec + lc4);
        rb[i] = *(const float4*)(W + (size_t)(bn + row) * Ec + lc4);
    }
    #pragma unroll
    for (int i = 0; i < 4; i++) {
        int row = lrw + i * 32;
        *(uint4*)&Abuf[0][row * 36 + lc4] = make_uint4(cvt_tf32(ra[i].x), cvt_tf32(ra[i].y),
                                                       cvt_tf32(ra[i].z), cvt_tf32(ra[i].w));
        *(uint4*)&Bbuf[0][row * 36 + lc4] = make_uint4(cvt_tf32(rb[i].x), cvt_tf32(rb[i].y),
                                                       cvt_tf32(rb[i].z), cvt_tf32(rb[i].w));
    }
    __syncthreads();

    for (int ks = 0; ks < 32; ks++) {
        const int cur = ks & 1;
        if (ks < 31) {
            #pragma unroll
            for (int i = 0; i < 4; i++) {
                int row = lrw + i * 32;
                ra[i] = *(const float4*)(A + (size_t)(bm + row) * Ec + (ks + 1) * 32 + lc4);
                rb[i] = *(const float4*)(W + (size_t)(bn + row) * Ec + (ks + 1) * 32 + lc4);
            }
        }
        #pragma unroll
        for (int k8 = 0; k8 < 4; k8++) {
            uint32_t af[4][4], bf[4][2];
            #pragma unroll
            for (int mt = 0; mt < 4; mt++)
                ldsm4(af[mt], sA[cur] + (uint32_t)(((aRow + mt * 16) * 36 + k8 * 8 + aCol) * 4));
            #pragma unroll
            for (int np = 0; np < 2; np++) {
                uint32_t t4[4];
                ldsm4(t4, sB[cur] + (uint32_t)(((bRow + np * 16) * 36 + k8 * 8 + bCol) * 4));
                bf[2*np][0] = t4[0]; bf[2*np][1] = t4[1];
                bf[2*np+1][0] = t4[2]; bf[2*np+1][1] = t4[3];
            }
            #pragma unroll
            for (int mt = 0; mt < 4; mt++)
                #pragma unroll
                for (int nt = 0; nt < 4; nt++)
                    mma_tf32(c[mt][nt], af[mt], bf[nt]);
        }
        if (ks < 31) {
            #pragma unroll
            for (int i = 0; i < 4; i++) {
                int row = lrw + i * 32;
                *(uint4*)&Abuf[cur ^ 1][row * 36 + lc4] =
                    make_uint4(cvt_tf32(ra[i].x), cvt_tf32(ra[i].y), cvt_tf32(ra[i].z), cvt_tf32(ra[i].w));
                *(uint4*)&Bbuf[cur ^ 1][row * 36 + lc4] =
                    make_uint4(cvt_tf32(rb[i].x), cvt_tf32(rb[i].y), cvt_tf32(rb[i].z), cvt_tf32(rb[i].w));
            }
        }
        __syncthreads();
    }

    const int lrow = lane >> 2;
    const int lk   = lane & 3;
    #pragma unroll
    for (int mt = 0; mt < 4; mt++) {
        #pragma unroll
        for (int half = 0; half < 2; half++) {
            int row = bm + wrow * 64 + mt * 16 + lrow + half * 8;
            #pragma unroll
            for (int nt = 0; nt < 4; nt++) {
                int col = bn + wcol * 32 + nt * 8 + lk * 2;
                float v0 = c[mt][nt][half * 2];
                float v1 = c[mt][nt][half * 2 + 1];
                if (MODE == 0) {
                    int b = row >> 11, t = row & 2047;
                    int h = col >> 6, d = col & 63;
                    *(uint32_t*)&hdst[(((size_t)(b * Hc + h)) * Tc + t) * HDc + d] =
                        pack_f16((v0 + bias[col]) * scale, (v1 + bias[col + 1]) * scale);
                } else {
                    *(float2*)&Cout[(size_t)row * Ec + col] =
                        make_float2(v0 + bias[col], v1 + bias[col + 1]);
                }
            }
        }
    }
}

// ---------------------------------------------------------------------------
// attn_fused (all-fp16 operands): per (bh, 64-row t-tile).
//   S = Q@K^T (fp16 m16n8k16, Q frags in regs), mask, raw S -> g_p (fp32),
//   online max/rescale, p = exp(S-m) fp16, O += P@V (fp16 mma, ldsm.trans).
// Writes g_o = O / sum and g_c = m + log(sum).
// ---------------------------------------------------------------------------
__global__ void __launch_bounds__(128, 4) attn_fused(
    const unsigned char* __restrict__ am, const unsigned char* __restrict__ kpm)
{
    __shared__ uint32_t Ks[64 * 36];   // Q staging, then K tiles (fp16, 72-half stride)
    __shared__ uint32_t Vs[64 * 36];   // V tiles (fp16, 72-half stride)

    const int tid  = threadIdx.x;
    const int w    = tid >> 5;
    const int lane = tid & 31;
    const int lrow = lane >> 2;
    const int lk   = lane & 3;
    const int tbase = blockIdx.x * 64;
    const int bh = blockIdx.y;
    const int b = bh >> 4, h = bh & 15;

    const __half* Q  = g_q + (size_t)bh * Tc * HDc;
    const __half* Kg = g_k + (size_t)bh * Sc * HDc;
    const __half* Vg = g_v + (size_t)bh * Sc * HDc;

    const uint32_t sK = smem_u32(Ks);
    const uint32_t sV = smem_u32(Vs);

    // fragment address components (shared by Q-A and K-B ldsm x4 patterns)
    const int fRow  = (lane & 7) + ((lane >> 3) & 1) * 8;   // 0..15
    const int fColH = (lane >> 4) * 8;                      // 0 or 8 (halves)

    // ---- stage Q tile (64x64 fp16) and load A-fragments into registers ----
    #pragma unroll
    for (int i = 0; i < 4; i++) {
        int flat = tid + i * 128;
        int row = flat >> 3, c8 = (flat & 7) * 8;
        *(uint4*)((char*)Ks + row * 144 + c8 * 2) =
            *(const uint4*)(Q + (size_t)(tbase + row) * HDc + c8);
    }
    __syncthreads();
    uint32_t aQ[4][4];
    #pragma unroll
    for (int ks = 0; ks < 4; ks++)
        ldsm4(aQ[ks], sK + (uint32_t)((w * 16 + fRow) * 144 + (ks * 16 + fColH) * 2));
    __syncthreads();

    float Oa[8][4];
    #pragma unroll
    for (int i = 0; i < 8; i++)
        #pragma unroll
        for (int u = 0; u < 4; u++) Oa[i][u] = 0.f;
    float m_lo = -1e30f, m_hi = -1e30f, s_lo = 0.f, s_hi = 0.f;

    const int t_lo = tbase + w * 16 + lrow;
    const int t_hi = t_lo + 8;

    for (int s0 = 0; s0 < Sc; s0 += 64) {
        // ---- stage K and V tiles (fp16 direct copy) ----
        #pragma unroll
        for (int i = 0; i < 4; i++) {
            int flat = tid + i * 128;
            int row = flat >> 3, c8 = (flat & 7) * 8;
            *(uint4*)((char*)Ks + row * 144 + c8 * 2) =
                *(const uint4*)(Kg + (size_t)(s0 + row) * HDc + c8);
            *(uint4*)((char*)Vs + row * 144 + c8 * 2) =
                *(const uint4*)(Vg + (size_t)(s0 + row) * HDc + c8);
        }
        __syncthreads();

        // ---- S = Q @ K^T  (fp16 m16n8k16) ----
        float S[8][4];
        #pragma unroll
        for (int nt = 0; nt < 8; nt++)
            #pragma unroll
            for (int u = 0; u < 4; u++) S[nt][u] = 0.f;
        #pragma unroll
        for (int ks = 0; ks < 4; ks++) {
            #pragma unroll
            for (int np = 0; np < 4; np++) {
                uint32_t t4[4];
                ldsm4(t4, sK + (uint32_t)((np * 16 + fRow) * 144 + (ks * 16 + fColH) * 2));
                mma_f16(S[2*np],     aQ[ks], t4[0], t4[2]);
                mma_f16(S[2*np + 1], aQ[ks], t4[1], t4[3]);
            }
        }

        // ---- mask, raw-score write (fp32), tile max ----
        float tmax_lo = -1e30f, tmax_hi = -1e30f;
        #pragma unroll
        for (int nt = 0; nt < 8; nt++) {
            int col = s0 + nt * 8 + lk * 2;
            uchar2 a0 = *(const uchar2*)&am[(size_t)t_lo * Sc + col];
            uchar2 a1 = *(const uchar2*)&am[(size_t)t_hi * Sc + col];
            uchar2 kp = *(const uchar2*)&kpm[(size_t)b * Sc + col];
            if (a0.x | kp.x) S[nt][0] = 1e-10f;
            if (a0.y | kp.y) S[nt][1] = 1e-10f;
            if (a1.x | kp.x) S[nt][2] = 1e-10f;
            if (a1.y | kp.y) S[nt][3] = 1e-10f;
            *(float2*)&g_p[((size_t)bh * Tc + t_lo) * Sc + col] = make_float2(S[nt][0], S[nt][1]);
            *(float2*)&g_p[((size_t)bh * Tc + t_hi) * Sc + col] = make_float2(S[nt][2], S[nt][3]);
            tmax_lo = fmaxf(tmax_lo, fmaxf(S[nt][0], S[nt][1]));
            tmax_hi = fmaxf(tmax_hi, fmaxf(S[nt][2], S[nt][3]));
        }
        tmax_lo = fmaxf(tmax_lo, __shfl_xor_sync(0xffffffffu, tmax_lo, 1));
        tmax_lo = fmaxf(tmax_lo, __shfl_xor_sync(0xffffffffu, tmax_lo, 2));
        tmax_hi = fmaxf(tmax_hi, __shfl_xor_sync(0xffffffffu, tmax_hi, 1));
        tmax_hi = fmaxf(tmax_hi, __shfl_xor_sync(0xffffffffu, tmax_hi, 2));

        // ---- online rescale ----
        float mnew_lo = fmaxf(m_lo, tmax_lo);
        float mnew_hi = fmaxf(m_hi, tmax_hi);
        float f_lo = __expf(m_lo - mnew_lo);
        float f_hi = __expf(m_hi - mnew_hi);
        m_lo = mnew_lo; m_hi = mnew_hi;
        s_lo *= f_lo;   s_hi *= f_hi;
        #pragma unroll
        for (int nd = 0; nd < 8; nd++) {
            Oa[nd][0] *= f_lo; Oa[nd][1] *= f_lo;
            Oa[nd][2] *= f_hi; Oa[nd][3] *= f_hi;
        }

        // ---- p = exp(S - m), sums, fp16 pack (C-frag == fp16 A-frag layout) ----
        uint32_t aP[4][4];
        #pragma unroll
        for (int nt = 0; nt < 8; nt++) {
            float p0 = __expf(S[nt][0] - m_lo);
            float p1 = __expf(S[nt][1] - m_lo);
            float p2 = __expf(S[nt][2] - m_hi);
            float p3 = __expf(S[nt][3] - m_hi);
            s_lo += p0 + p1;
            s_hi += p2 + p3;
            int kk = nt >> 1, hi = (nt & 1) * 2;
            aP[kk][hi]     = pack_f16(p0, p1);
            aP[kk][hi + 1] = pack_f16(p2, p3);
        }

        // ---- O += P @ V  (fp16 m16n8k16, B via ldmatrix.trans) ----
        #pragma unroll
        for (int kk = 0; kk < 4; kk++) {
            int vrow = kk * 16 + fRow;
            #pragma unroll
            for (int nd16 = 0; nd16 < 4; nd16++) {
                uint32_t t4[4];
                int vcol = nd16 * 16 + (lane >> 4) * 8;
                ldsm4t(t4, sV + (uint32_t)(vrow * 144 + vcol * 2));
                mma_f16(Oa[nd16 * 2],     aP[kk], t4[0], t4[1]);
                mma_f16(Oa[nd16 * 2 + 1], aP[kk], t4[2], t4[3]);
            }
        }
        __syncthreads();
    }

    // ---- epilogue ----
    float r_lo = s_lo, r_hi = s_hi;
    r_lo += __shfl_xor_sync(0xffffffffu, r_lo, 1);
    r_lo += __shfl_xor_sync(0xffffffffu, r_lo, 2);
    r_hi += __shfl_xor_sync(0xffffffffu, r_hi, 1);
    r_hi += __shfl_xor_sync(0xffffffffu, r_hi, 2);
    const float inv_lo = 1.0f / r_lo;
    const float inv_hi = 1.0f / r_hi;

    #pragma unroll
    for (int nd = 0; nd < 8; nd++) {
        int d = nd * 8 + lk * 2;
        *(float2*)&g_o[(((size_t)b * Tc + t_lo) * Hc + h) * HDc + d] =
            make_float2(Oa[nd][0] * inv_lo, Oa[nd][1] * inv_lo);
        *(float2*)&g_o[(((size_t)b * Tc + t_hi) * Hc + h) * HDc + d] =
            make_float2(Oa[nd][2] * inv_hi, Oa[nd][3] * inv_hi);
    }
    if (lk == 0) {
        g_c[(size_t)bh * Tc + t_lo] = m_lo + __logf(r_lo);
        g_c[(size_t)bh * Tc + t_hi] = m_hi + __logf(r_hi);
    }
}

// ---------------------------------------------------------------------------
// headmax: attn_max[b,t,s] = exp(max_h (score[b,h,t,s] - c[b,h,t]))
// ---------------------------------------------------------------------------
__global__ void __launch_bounds__(256) headmax_kernel(float* __restrict__ out2)
{
    size_t i4 = (size_t)blockIdx.x * 256 + threadIdx.x;
    size_t sq = i4 % (Sc / 4);
    size_t bt = i4 / (Sc / 4);
    size_t b = bt >> 11, t = bt & 2047;
    size_t s = sq * 4;

    float4 best = make_float4(-1e30f, -1e30f, -1e30f, -1e30f);
    #pragma unroll
    for (int h = 0; h < Hc; h++) {
        size_t bh = b * Hc + h;
        float ch = g_c[bh * Tc + t];
        float4 sc = *(const float4*)&g_p[(bh * Tc + t) * Sc + s];
        best.x = fmaxf(best.x, sc.x - ch);
        best.y = fmaxf(best.y, sc.y - ch);
        best.z = fmaxf(best.z, sc.z - ch);
        best.w = fmaxf(best.w, sc.w - ch);
    }
    *(float4*)&out2[bt * Sc + s] =
        make_float4(__expf(best.x), __expf(best.y), __expf(best.z), __expf(best.w));
}

// ---------------------------------------------------------------------------
extern "C" void kernel_launch(void* const* d_in, const int* in_sizes, int n_in,
                              void* d_out, int out_size)
{
    const float* query = (const float*)d_in[0];
    const float* key   = (const float*)d_in[1];
    const float* value = (const float*)d_in[2];
    const unsigned char* kpm = (const unsigned char*)d_in[3];
    const unsigned char* am  = (const unsigned char*)d_in[4];
    const float* Wq = (const float*)d_in[5];
    const float* bq = (const float*)d_in[6];
    const float* Wk = (const float*)d_in[7];
    const float* bk = (const float*)d_in[8];
    const float* Wv = (const float*)d_in[9];
    const float* bv = (const float*)d_in[10];
    const float* Wo = (const float*)d_in[11];
    const float* bo = (const float*)d_in[12];

    float* out      = (float*)d_out;
    float* attn_max = (float*)d_out + (size_t)Bc * Tc * Ec;

    float *po;
    cudaGetSymbolAddress((void**)&po, g_o);

    static cudaStream_t s2 = nullptr;
    static cudaEvent_t evFork = nullptr, evJoin = nullptr;
    if (s2 == nullptr) {
        cudaStreamCreateWithFlags(&s2, cudaStreamNonBlocking);
        cudaEventCreateWithFlags(&evFork, cudaEventDisableTiming);
        cudaEventCreateWithFlags(&evJoin, cudaEventDisableTiming);
    }

    const int GEMM_SMEM = 4 * 128 * 36 * 4;   // 73728 (double buffer)
    cudaFuncSetAttribute(gemm_db<0>, cudaFuncAttributeMaxDynamicSharedMemorySize, GEMM_SMEM);
    cudaFuncSetAttribute(gemm_db<3>, cudaFuncAttributeMaxDynamicSharedMemorySize, GEMM_SMEM);

    dim3 thr(256);

    // Batched Q/K/V projections -> fp16 (grid.z = 0,1,2)
    gemm_db<0><<<dim3(Ec / 128, (Bc * Tc) / 128, 3), thr, GEMM_SMEM>>>(
        query, key, value, Wq, Wk, Wv, bq, bk, bv, nullptr);

    // Fused score + online softmax + P@V  (raw scores -> g_p, stats -> g_c)
    attn_fused<<<dim3(Tc / 64, Bc * Hc), dim3(128)>>>(am, kpm);

    // fork: headmax on side stream, out-projection on main stream, then join
    cudaEventRecord(evFork, 0);
    cudaStreamWaitEvent(s2, evFork, 0);

    headmax_kernel<<<dim3((unsigned)(((size_t)Bc * Tc * Sc / 4) / 256)), thr, 0, s2>>>(attn_max);

    gemm_db<3><<<dim3(Ec / 128, (Bc * Tc) / 128, 1), thr, GEMM_SMEM>>>(
        po, nullptr, nullptr, Wo, nullptr, nullptr, bo, nullptr, nullptr, out);

    cudaEventRecord(evJoin, s2);
    cudaStreamWaitEvent(0, evJoin, 0);
}

// round 13
// speedup vs baseline: 1.8004x; 1.1197x over previous
#include <cuda_runtime.h>
#include <cuda_fp16.h>
#include <cstdint>
#include <math.h>

#define Bc 2
#define Tc 2048
#define Sc 2048
#define Ec 1024
#define Hc 16
#define HDc 64
#define QSCALE 0.125f

// Scratch (__device__ globals; allocation-free)
__device__ __half g_q[(size_t)Bc*Hc*Tc*HDc];  // [bh,t,d] fp16
__device__ __half g_k[(size_t)Bc*Hc*Sc*HDc];  // [bh,s,d] fp16
__device__ __half g_v[(size_t)Bc*Hc*Sc*HDc];  // [bh,s,d] fp16
__device__ float  g_o[(size_t)Bc*Tc*Ec];      // [b,t,h,d]  attn out pre-Wo
__device__ float  g_p[(size_t)Bc*Hc*Tc*Sc];   // [bh,t,s]   raw masked scores (512 MB)
__device__ float  g_c[Bc*Hc*Tc];              // m + log(sum)

__device__ __forceinline__ uint32_t smem_u32(const void* p) {
    uint32_t a;
    asm("{ .reg .u64 t; cvta.to.shared.u64 t, %1; cvt.u32.u64 %0, t; }" : "=r"(a) : "l"(p));
    return a;
}
__device__ __forceinline__ void mma_f16(float c[4], const uint32_t a[4], uint32_t b0, uint32_t b1) {
    asm volatile(
        "mma.sync.aligned.m16n8k16.row.col.f32.f16.f16.f32 "
        "{%0,%1,%2,%3}, {%4,%5,%6,%7}, {%8,%9}, {%0,%1,%2,%3};"
        : "+f"(c[0]), "+f"(c[1]), "+f"(c[2]), "+f"(c[3])
        : "r"(a[0]), "r"(a[1]), "r"(a[2]), "r"(a[3]), "r"(b0), "r"(b1));
}
__device__ __forceinline__ void ldsm4(uint32_t r[4], uint32_t addr) {
    asm volatile("ldmatrix.sync.aligned.m8n8.x4.shared.b16 {%0,%1,%2,%3}, [%4];"
        : "=r"(r[0]), "=r"(r[1]), "=r"(r[2]), "=r"(r[3]) : "r"(addr));
}
__device__ __forceinline__ void ldsm4t(uint32_t r[4], uint32_t addr) {
    asm volatile("ldmatrix.sync.aligned.m8n8.x4.trans.shared.b16 {%0,%1,%2,%3}, [%4];"
        : "=r"(r[0]), "=r"(r[1]), "=r"(r[2]), "=r"(r[3]) : "r"(addr));
}
__device__ __forceinline__ uint32_t pack_f16(float lo, float hi) {
    uint32_t r; asm("cvt.rn.f16x2.f32 %0, %1, %2;" : "=r"(r) : "f"(hi), "f"(lo)); return r;
}

// ---------------------------------------------------------------------------
// Double-buffered fp16 GEMM (fp32 in, fp16 operands, fp32 accum):
//   C = A[M,1024] @ W[1024,1024]^T (+bias)
// MODE 0: batched QKV projection (blockIdx.z selects q/k/v) -> fp16 g_q/g_k/g_v
// MODE 3: output projection (flat fp32 [row, col] out)
// BM=BN=128, BK=32; 8 warps 2x4; smem row stride 40 halves (conflict-free).
// ---------------------------------------------------------------------------
template<int MODE>
__global__ void __launch_bounds__(256, 2) gemm_db(
    const float* __restrict__ A0, const float* __restrict__ A1, const float* __restrict__ A2,
    const float* __restrict__ W0, const float* __restrict__ W1, const float* __restrict__ W2,
    const float* __restrict__ bias0, const float* __restrict__ bias1, const float* __restrict__ bias2,
    float* __restrict__ Cout)
{
    extern __shared__ uint32_t ds[];
    // fp16 tiles: 128 rows x 40-half stride = 2560 uint32 each
    uint32_t* const Abuf[2] = { ds,        ds + 5120 };
    uint32_t* const Bbuf[2] = { ds + 2560, ds + 7680 };

    const int tid  = threadIdx.x;
    const int wid  = tid >> 5;
    const int lane = tid & 31;
    const int wrow = wid >> 2;        // 0..1
    const int wcol = wid & 3;         // 0..3
    const int bm = blockIdx.y * 128;
    const int bn = blockIdx.x * 128;
    const int z  = blockIdx.z;

    const float* A; const float* W; const float* bias; float scale;
    __half* hdst = nullptr;
    if (MODE == 0) {
        A    = (z == 0) ? A0 : (z == 1) ? A1 : A2;
        W    = (z == 0) ? W0 : (z == 1) ? W1 : W2;
        bias = (z == 0) ? bias0 : (z == 1) ? bias1 : bias2;
        scale = (z == 0) ? QSCALE : 1.0f;
        hdst = (z == 0) ? g_q : (z == 1) ? g_k : g_v;
    } else {
        A = A0; W = W0; bias = bias0; scale = 1.0f;
    }

    float c[4][4][4];
    #pragma unroll
    for (int i = 0; i < 4; i++)
        #pragma unroll
        for (int j = 0; j < 4; j++)
            #pragma unroll
            for (int u = 0; u < 4; u++) c[i][j][u] = 0.f;

    // fragment address components (validated fp16 ldsm patterns)
    const int fRow  = (lane & 7) + ((lane >> 3) & 1) * 8;   // 0..15
    const int fColH = (lane >> 4) * 8;                      // 0 or 8 (halves)
    const uint32_t sA[2] = { smem_u32(Abuf[0]), smem_u32(Abuf[1]) };
    const uint32_t sB[2] = { smem_u32(Bbuf[0]), smem_u32(Bbuf[1]) };

    const int lrw = tid >> 3;          // load row base (0..31, step 32)
    const int lc4 = (tid & 7) * 4;     // load col (floats)

    float4 ra[4], rb[4];
    #pragma unroll
    for (int i = 0; i < 4; i++) {
        int row = lrw + i * 32;
        ra[i] = *(const float4*)(A + (size_t)(bm + row) * Ec + lc4);
        rb[i] = *(const float4*)(W + (size_t)(bn + row) * Ec + lc4);
    }
    #pragma unroll
    for (int i = 0; i < 4; i++) {
        int row = lrw + i * 32;
        int idx = row * 20 + (lc4 >> 1);
        *(uint2*)&Abuf[0][idx] = make_uint2(pack_f16(ra[i].x, ra[i].y), pack_f16(ra[i].z, ra[i].w));
        *(uint2*)&Bbuf[0][idx] = make_uint2(pack_f16(rb[i].x, rb[i].y), pack_f16(rb[i].z, rb[i].w));
    }
    __syncthreads();

    for (int ks = 0; ks < 32; ks++) {
        const int cur = ks & 1;
        if (ks < 31) {
            #pragma unroll
            for (int i = 0; i < 4; i++) {
                int row = lrw + i * 32;
                ra[i] = *(const float4*)(A + (size_t)(bm + row) * Ec + (ks + 1) * 32 + lc4);
                rb[i] = *(const float4*)(W + (size_t)(bn + row) * Ec + (ks + 1) * 32 + lc4);
            }
        }
        #pragma unroll
        for (int k16 = 0; k16 < 2; k16++) {
            uint32_t af[4][4], bf[4][2];
            #pragma unroll
            for (int mt = 0; mt < 4; mt++)
                ldsm4(af[mt], sA[cur] + (uint32_t)(((wrow * 64 + mt * 16 + fRow) * 40
                                                    + k16 * 16 + fColH) * 2));
            #pragma unroll
            for (int np = 0; np < 2; np++) {
                uint32_t t4[4];
                ldsm4(t4, sB[cur] + (uint32_t)(((wcol * 32 + np * 16 + fRow) * 40
                                                + k16 * 16 + fColH) * 2));
                bf[2*np][0] = t4[0]; bf[2*np][1] = t4[2];
                bf[2*np+1][0] = t4[1]; bf[2*np+1][1] = t4[3];
            }
            #pragma unroll
            for (int mt = 0; mt < 4; mt++)
                #pragma unroll
                for (int nt = 0; nt < 4; nt++)
                    mma_f16(c[mt][nt], af[mt], bf[nt][0], bf[nt][1]);
        }
        if (ks < 31) {
            #pragma unroll
            for (int i = 0; i < 4; i++) {
                int row = lrw + i * 32;
                int idx = row * 20 + (lc4 >> 1);
                *(uint2*)&Abuf[cur ^ 1][idx] = make_uint2(pack_f16(ra[i].x, ra[i].y),
                                                          pack_f16(ra[i].z, ra[i].w));
                *(uint2*)&Bbuf[cur ^ 1][idx] = make_uint2(pack_f16(rb[i].x, rb[i].y),
                                                          pack_f16(rb[i].z, rb[i].w));
            }
        }
        __syncthreads();
    }

    const int lrow = lane >> 2;
    const int lk   = lane & 3;
    #pragma unroll
    for (int mt = 0; mt < 4; mt++) {
        #pragma unroll
        for (int half = 0; half < 2; half++) {
            int row = bm + wrow * 64 + mt * 16 + lrow + half * 8;
            #pragma unroll
            for (int nt = 0; nt < 4; nt++) {
                int col = bn + wcol * 32 + nt * 8 + lk * 2;
                float v0 = c[mt][nt][half * 2];
                float v1 = c[mt][nt][half * 2 + 1];
                if (MODE == 0) {
                    int b = row >> 11, t = row & 2047;
                    int h = col >> 6, d = col & 63;
                    *(uint32_t*)&hdst[(((size_t)(b * Hc + h)) * Tc + t) * HDc + d] =
                        pack_f16((v0 + bias[col]) * scale, (v1 + bias[col + 1]) * scale);
                } else {
                    *(float2*)&Cout[(size_t)row * Ec + col] =
                        make_float2(v0 + bias[col], v1 + bias[col + 1]);
                }
            }
        }
    }
}

// ---------------------------------------------------------------------------
// attn_fused (all-fp16 operands): per (bh, 64-row t-tile).
//   S = Q@K^T (fp16 m16n8k16, Q frags in regs), mask, raw S -> g_p (fp32),
//   online max/rescale, p = exp(S-m) fp16, O += P@V (fp16 mma, ldsm.trans).
// Writes g_o = O / sum and g_c = m + log(sum).
// ---------------------------------------------------------------------------
__global__ void __launch_bounds__(128, 4) attn_fused(
    const unsigned char* __restrict__ am, const unsigned char* __restrict__ kpm)
{
    __shared__ uint32_t Ks[64 * 36];   // Q staging, then K tiles (fp16, 72-half stride)
    __shared__ uint32_t Vs[64 * 36];   // V tiles (fp16, 72-half stride)

    const int tid  = threadIdx.x;
    const int w    = tid >> 5;
    const int lane = tid & 31;
    const int lrow = lane >> 2;
    const int lk   = lane & 3;
    const int tbase = blockIdx.x * 64;
    const int bh = blockIdx.y;
    const int b = bh >> 4, h = bh & 15;

    const __half* Q  = g_q + (size_t)bh * Tc * HDc;
    const __half* Kg = g_k + (size_t)bh * Sc * HDc;
    const __half* Vg = g_v + (size_t)bh * Sc * HDc;

    const uint32_t sK = smem_u32(Ks);
    const uint32_t sV = smem_u32(Vs);

    const int fRow  = (lane & 7) + ((lane >> 3) & 1) * 8;   // 0..15
    const int fColH = (lane >> 4) * 8;                      // 0 or 8 (halves)

    // ---- stage Q tile (64x64 fp16) and load A-fragments into registers ----
    #pragma unroll
    for (int i = 0; i < 4; i++) {
        int flat = tid + i * 128;
        int row = flat >> 3, c8 = (flat & 7) * 8;
        *(uint4*)((char*)Ks + row * 144 + c8 * 2) =
            *(const uint4*)(Q + (size_t)(tbase + row) * HDc + c8);
    }
    __syncthreads();
    uint32_t aQ[4][4];
    #pragma unroll
    for (int ks = 0; ks < 4; ks++)
        ldsm4(aQ[ks], sK + (uint32_t)((w * 16 + fRow) * 144 + (ks * 16 + fColH) * 2));
    __syncthreads();

    float Oa[8][4];
    #pragma unroll
    for (int i = 0; i < 8; i++)
        #pragma unroll
        for (int u = 0; u < 4; u++) Oa[i][u] = 0.f;
    float m_lo = -1e30f, m_hi = -1e30f, s_lo = 0.f, s_hi = 0.f;

    const int t_lo = tbase + w * 16 + lrow;
    const int t_hi = t_lo + 8;

    for (int s0 = 0; s0 < Sc; s0 += 64) {
        // ---- stage K and V tiles (fp16 direct copy) ----
        #pragma unroll
        for (int i = 0; i < 4; i++) {
            int flat = tid + i * 128;
            int row = flat >> 3, c8 = (flat & 7) * 8;
            *(uint4*)((char*)Ks + row * 144 + c8 * 2) =
                *(const uint4*)(Kg + (size_t)(s0 + row) * HDc + c8);
            *(uint4*)((char*)Vs + row * 144 + c8 * 2) =
                *(const uint4*)(Vg + (size_t)(s0 + row) * HDc + c8);
        }
        __syncthreads();

        // ---- S = Q @ K^T  (fp16 m16n8k16) ----
        float S[8][4];
        #pragma unroll
        for (int nt = 0; nt < 8; nt++)
            #pragma unroll
            for (int u = 0; u < 4; u++) S[nt][u] = 0.f;
        #pragma unroll
        for (int ks = 0; ks < 4; ks++) {
            #pragma unroll
            for (int np = 0; np < 4; np++) {
                uint32_t t4[4];
                ldsm4(t4, sK + (uint32_t)((np * 16 + fRow) * 144 + (ks * 16 + fColH) * 2));
                mma_f16(S[2*np],     aQ[ks], t4[0], t4[2]);
                mma_f16(S[2*np + 1], aQ[ks], t4[1], t4[3]);
            }
        }

        // ---- mask, raw-score write (fp32), tile max ----
        float tmax_lo = -1e30f, tmax_hi = -1e30f;
        #pragma unroll
        for (int nt = 0; nt < 8; nt++) {
            int col = s0 + nt * 8 + lk * 2;
            uchar2 a0 = *(const uchar2*)&am[(size_t)t_lo * Sc + col];
            uchar2 a1 = *(const uchar2*)&am[(size_t)t_hi * Sc + col];
            uchar2 kp = *(const uchar2*)&kpm[(size_t)b * Sc + col];
            if (a0.x | kp.x) S[nt][0] = 1e-10f;
            if (a0.y | kp.y) S[nt][1] = 1e-10f;
            if (a1.x | kp.x) S[nt][2] = 1e-10f;
            if (a1.y | kp.y) S[nt][3] = 1e-10f;
            *(float2*)&g_p[((size_t)bh * Tc + t_lo) * Sc + col] = make_float2(S[nt][0], S[nt][1]);
            *(float2*)&g_p[((size_t)bh * Tc + t_hi) * Sc + col] = make_float2(S[nt][2], S[nt][3]);
            tmax_lo = fmaxf(tmax_lo, fmaxf(S[nt][0], S[nt][1]));
            tmax_hi = fmaxf(tmax_hi, fmaxf(S[nt][2], S[nt][3]));
        }
        tmax_lo = fmaxf(tmax_lo, __shfl_xor_sync(0xffffffffu, tmax_lo, 1));
        tmax_lo = fmaxf(tmax_lo, __shfl_xor_sync(0xffffffffu, tmax_lo, 2));
        tmax_hi = fmaxf(tmax_hi, __shfl_xor_sync(0xffffffffu, tmax_hi, 1));
        tmax_hi = fmaxf(tmax_hi, __shfl_xor_sync(0xffffffffu, tmax_hi, 2));

        // ---- online rescale ----
        float mnew_lo = fmaxf(m_lo, tmax_lo);
        float mnew_hi = fmaxf(m_hi, tmax_hi);
        float f_lo = __expf(m_lo - mnew_lo);
        float f_hi = __expf(m_hi - mnew_hi);
        m_lo = mnew_lo; m_hi = mnew_hi;
        s_lo *= f_lo;   s_hi *= f_hi;
        #pragma unroll
        for (int nd = 0; nd < 8; nd++) {
            Oa[nd][0] *= f_lo; Oa[nd][1] *= f_lo;
            Oa[nd][2] *= f_hi; Oa[nd][3] *= f_hi;
        }

        // ---- p = exp(S - m), sums, fp16 pack (C-frag == fp16 A-frag layout) ----
        uint32_t aP[4][4];
        #pragma unroll
        for (int nt = 0; nt < 8; nt++) {
            float p0 = __expf(S[nt][0] - m_lo);
            float p1 = __expf(S[nt][1] - m_lo);
            float p2 = __expf(S[nt][2] - m_hi);
            float p3 = __expf(S[nt][3] - m_hi);
            s_lo += p0 + p1;
            s_hi += p2 + p3;
            int kk = nt >> 1, hi = (nt & 1) * 2;
            aP[kk][hi]     = pack_f16(p0, p1);
            aP[kk][hi + 1] = pack_f16(p2, p3);
        }

        // ---- O += P @ V  (fp16 m16n8k16, B via ldmatrix.trans) ----
        #pragma unroll
        for (int kk = 0; kk < 4; kk++) {
            int vrow = kk * 16 + fRow;
            #pragma unroll
            for (int nd16 = 0; nd16 < 4; nd16++) {
                uint32_t t4[4];
                int vcol = nd16 * 16 + (lane >> 4) * 8;
                ldsm4t(t4, sV + (uint32_t)(vrow * 144 + vcol * 2));
                mma_f16(Oa[nd16 * 2],     aP[kk], t4[0], t4[1]);
                mma_f16(Oa[nd16 * 2 + 1], aP[kk], t4[2], t4[3]);
            }
        }
        __syncthreads();
    }

    // ---- epilogue ----
    float r_lo = s_lo, r_hi = s_hi;
    r_lo += __shfl_xor_sync(0xffffffffu, r_lo, 1);
    r_lo += __shfl_xor_sync(0xffffffffu, r_lo, 2);
    r_hi += __shfl_xor_sync(0xffffffffu, r_hi, 1);
    r_hi += __shfl_xor_sync(0xffffffffu, r_hi, 2);
    const float inv_lo = 1.0f / r_lo;
    const float inv_hi = 1.0f / r_hi;

    #pragma unroll
    for (int nd = 0; nd < 8; nd++) {
        int d = nd * 8 + lk * 2;
        *(float2*)&g_o[(((size_t)b * Tc + t_lo) * Hc + h) * HDc + d] =
            make_float2(Oa[nd][0] * inv_lo, Oa[nd][1] * inv_lo);
        *(float2*)&g_o[(((size_t)b * Tc + t_hi) * Hc + h) * HDc + d] =
            make_float2(Oa[nd][2] * inv_hi, Oa[nd][3] * inv_hi);
    }
    if (lk == 0) {
        g_c[(size_t)bh * Tc + t_lo] = m_lo + __logf(r_lo);
        g_c[(size_t)bh * Tc + t_hi] = m_hi + __logf(r_hi);
    }
}

// ---------------------------------------------------------------------------
// headmax: attn_max[b,t,s] = exp(max_h (score[b,h,t,s] - c[b,h,t]))
// ---------------------------------------------------------------------------
__global__ void __launch_bounds__(256) headmax_kernel(float* __restrict__ out2)
{
    size_t i4 = (size_t)blockIdx.x * 256 + threadIdx.x;
    size_t sq = i4 % (Sc / 4);
    size_t bt = i4 / (Sc / 4);
    size_t b = bt >> 11, t = bt & 2047;
    size_t s = sq * 4;

    float4 best = make_float4(-1e30f, -1e30f, -1e30f, -1e30f);
    #pragma unroll
    for (int h = 0; h < Hc; h++) {
        size_t bh = b * Hc + h;
        float ch = g_c[bh * Tc + t];
        float4 sc = *(const float4*)&g_p[(bh * Tc + t) * Sc + s];
        best.x = fmaxf(best.x, sc.x - ch);
        best.y = fmaxf(best.y, sc.y - ch);
        best.z = fmaxf(best.z, sc.z - ch);
        best.w = fmaxf(best.w, sc.w - ch);
    }
    *(float4*)&out2[bt * Sc + s] =
        make_float4(__expf(best.x), __expf(best.y), __expf(best.z), __expf(best.w));
}

// ---------------------------------------------------------------------------
extern "C" void kernel_launch(void* const* d_in, const int* in_sizes, int n_in,
                              void* d_out, int out_size)
{
    const float* query = (const float*)d_in[0];
    const float* key   = (const float*)d_in[1];
    const float* value = (const float*)d_in[2];
    const unsigned char* kpm = (const unsigned char*)d_in[3];
    const unsigned char* am  = (const unsigned char*)d_in[4];
    const float* Wq = (const float*)d_in[5];
    const float* bq = (const float*)d_in[6];
    const float* Wk = (const float*)d_in[7];
    const float* bk = (const float*)d_in[8];
    const float* Wv = (const float*)d_in[9];
    const float* bv = (const float*)d_in[10];
    const float* Wo = (const float*)d_in[11];
    const float* bo = (const float*)d_in[12];

    float* out      = (float*)d_out;
    float* attn_max = (float*)d_out + (size_t)Bc * Tc * Ec;

    float *po;
    cudaGetSymbolAddress((void**)&po, g_o);

    static cudaStream_t s2 = nullptr;
    static cudaEvent_t evFork = nullptr, evJoin = nullptr;
    if (s2 == nullptr) {
        cudaStreamCreateWithFlags(&s2, cudaStreamNonBlocking);
        cudaEventCreateWithFlags(&evFork, cudaEventDisableTiming);
        cudaEventCreateWithFlags(&evJoin, cudaEventDisableTiming);
    }

    const int GEMM_SMEM = 4 * 2560 * 4;   // 40960 B (fp16 double buffer)
    cudaFuncSetAttribute(gemm_db<0>, cudaFuncAttributeMaxDynamicSharedMemorySize, GEMM_SMEM);
    cudaFuncSetAttribute(gemm_db<3>, cudaFuncAttributeMaxDynamicSharedMemorySize, GEMM_SMEM);

    dim3 thr(256);

    // Batched Q/K/V projections -> fp16 (grid.z = 0,1,2)
    gemm_db<0><<<dim3(Ec / 128, (Bc * Tc) / 128, 3), thr, GEMM_SMEM>>>(
        query, key, value, Wq, Wk, Wv, bq, bk, bv, nullptr);

    // Fused score + online softmax + P@V  (raw scores -> g_p, stats -> g_c)
    attn_fused<<<dim3(Tc / 64, Bc * Hc), dim3(128)>>>(am, kpm);

    // fork: headmax on side stream, out-projection on main stream, then join
    cudaEventRecord(evFork, 0);
    cudaStreamWaitEvent(s2, evFork, 0);

    headmax_kernel<<<dim3((unsigned)(((size_t)Bc * Tc * Sc / 4) / 256)), thr, 0, s2>>>(attn_max);

    gemm_db<3><<<dim3(Ec / 128, (Bc * Tc) / 128, 1), thr, GEMM_SMEM>>>(
        po, nullptr, nullptr, Wo, nullptr, nullptr, bo, nullptr, nullptr, out);

    cudaEventRecord(evJoin, s2);
    cudaStreamWaitEvent(0, evJoin, 0);
}

// round 14
// speedup vs baseline: 2.0811x; 1.1559x over previous
#include <cuda_runtime.h>
#include <cuda_fp16.h>
#include <cstdint>
#include <math.h>

#define Bc 2
#define Tc 2048
#define Sc 2048
#define Ec 1024
#define Hc 16
#define HDc 64
#define QSCALE 0.125f

// Scratch (__device__ globals; allocation-free)
__device__ __half g_q[(size_t)Bc*Hc*Tc*HDc];  // [bh,t,d] fp16
__device__ __half g_k[(size_t)Bc*Hc*Sc*HDc];  // [bh,s,d] fp16
__device__ __half g_v[(size_t)Bc*Hc*Sc*HDc];  // [bh,s,d] fp16
__device__ float  g_o[(size_t)Bc*Tc*Ec];      // [b,t,h,d]  attn out pre-Wo
__device__ float  g_c[Bc*Hc*Tc];              // m + log(sum)

__device__ __forceinline__ uint32_t smem_u32(const void* p) {
    uint32_t a;
    asm("{ .reg .u64 t; cvta.to.shared.u64 t, %1; cvt.u32.u64 %0, t; }" : "=r"(a) : "l"(p));
    return a;
}
__device__ __forceinline__ void mma_f16(float c[4], const uint32_t a[4], uint32_t b0, uint32_t b1) {
    asm volatile(
        "mma.sync.aligned.m16n8k16.row.col.f32.f16.f16.f32 "
        "{%0,%1,%2,%3}, {%4,%5,%6,%7}, {%8,%9}, {%0,%1,%2,%3};"
        : "+f"(c[0]), "+f"(c[1]), "+f"(c[2]), "+f"(c[3])
        : "r"(a[0]), "r"(a[1]), "r"(a[2]), "r"(a[3]), "r"(b0), "r"(b1));
}
__device__ __forceinline__ void ldsm4(uint32_t r[4], uint32_t addr) {
    asm volatile("ldmatrix.sync.aligned.m8n8.x4.shared.b16 {%0,%1,%2,%3}, [%4];"
        : "=r"(r[0]), "=r"(r[1]), "=r"(r[2]), "=r"(r[3]) : "r"(addr));
}
__device__ __forceinline__ void ldsm4t(uint32_t r[4], uint32_t addr) {
    asm volatile("ldmatrix.sync.aligned.m8n8.x4.trans.shared.b16 {%0,%1,%2,%3}, [%4];"
        : "=r"(r[0]), "=r"(r[1]), "=r"(r[2]), "=r"(r[3]) : "r"(addr));
}
__device__ __forceinline__ uint32_t pack_f16(float lo, float hi) {
    uint32_t r; asm("cvt.rn.f16x2.f32 %0, %1, %2;" : "=r"(r) : "f"(hi), "f"(lo)); return r;
}

// ---------------------------------------------------------------------------
// Double-buffered fp16 GEMM (fp32 in, fp16 operands, fp32 accum):
//   C = A[M,1024] @ W[1024,1024]^T (+bias)
// MODE 0: batched QKV projection (blockIdx.z selects q/k/v) -> fp16 g_q/g_k/g_v
// MODE 3: output projection (flat fp32 [row, col] out)
// ---------------------------------------------------------------------------
template<int MODE>
__global__ void __launch_bounds__(256, 2) gemm_db(
    const float* __restrict__ A0, const float* __restrict__ A1, const float* __restrict__ A2,
    const float* __restrict__ W0, const float* __restrict__ W1, const float* __restrict__ W2,
    const float* __restrict__ bias0, const float* __restrict__ bias1, const float* __restrict__ bias2,
    float* __restrict__ Cout)
{
    extern __shared__ uint32_t ds[];
    uint32_t* const Abuf[2] = { ds,        ds + 5120 };
    uint32_t* const Bbuf[2] = { ds + 2560, ds + 7680 };

    const int tid  = threadIdx.x;
    const int wid  = tid >> 5;
    const int lane = tid & 31;
    const int wrow = wid >> 2;
    const int wcol = wid & 3;
    const int bm = blockIdx.y * 128;
    const int bn = blockIdx.x * 128;
    const int z  = blockIdx.z;

    const float* A; const float* W; const float* bias; float scale;
    __half* hdst = nullptr;
    if (MODE == 0) {
        A    = (z == 0) ? A0 : (z == 1) ? A1 : A2;
        W    = (z == 0) ? W0 : (z == 1) ? W1 : W2;
        bias = (z == 0) ? bias0 : (z == 1) ? bias1 : bias2;
        scale = (z == 0) ? QSCALE : 1.0f;
        hdst = (z == 0) ? g_q : (z == 1) ? g_k : g_v;
    } else {
        A = A0; W = W0; bias = bias0; scale = 1.0f;
    }

    float c[4][4][4];
    #pragma unroll
    for (int i = 0; i < 4; i++)
        #pragma unroll
        for (int j = 0; j < 4; j++)
            #pragma unroll
            for (int u = 0; u < 4; u++) c[i][j][u] = 0.f;

    const int fRow  = (lane & 7) + ((lane >> 3) & 1) * 8;
    const int fColH = (lane >> 4) * 8;
    const uint32_t sA[2] = { smem_u32(Abuf[0]), smem_u32(Abuf[1]) };
    const uint32_t sB[2] = { smem_u32(Bbuf[0]), smem_u32(Bbuf[1]) };

    const int lrw = tid >> 3;
    const int lc4 = (tid & 7) * 4;

    float4 ra[4], rb[4];
    #pragma unroll
    for (int i = 0; i < 4; i++) {
        int row = lrw + i * 32;
        ra[i] = *(const float4*)(A + (size_t)(bm + row) * Ec + lc4);
        rb[i] = *(const float4*)(W + (size_t)(bn + row) * Ec + lc4);
    }
    #pragma unroll
    for (int i = 0; i < 4; i++) {
        int row = lrw + i * 32;
        int idx = row * 20 + (lc4 >> 1);
        *(uint2*)&Abuf[0][idx] = make_uint2(pack_f16(ra[i].x, ra[i].y), pack_f16(ra[i].z, ra[i].w));
        *(uint2*)&Bbuf[0][idx] = make_uint2(pack_f16(rb[i].x, rb[i].y), pack_f16(rb[i].z, rb[i].w));
    }
    __syncthreads();

    for (int ks = 0; ks < 32; ks++) {
        const int cur = ks & 1;
        if (ks < 31) {
            #pragma unroll
            for (int i = 0; i < 4; i++) {
                int row = lrw + i * 32;
                ra[i] = *(const float4*)(A + (size_t)(bm + row) * Ec + (ks + 1) * 32 + lc4);
                rb[i] = *(const float4*)(W + (size_t)(bn + row) * Ec + (ks + 1) * 32 + lc4);
            }
        }
        #pragma unroll
        for (int k16 = 0; k16 < 2; k16++) {
            uint32_t af[4][4], bf[4][2];
            #pragma unroll
            for (int mt = 0; mt < 4; mt++)
                ldsm4(af[mt], sA[cur] + (uint32_t)(((wrow * 64 + mt * 16 + fRow) * 40
                                                    + k16 * 16 + fColH) * 2));
            #pragma unroll
            for (int np = 0; np < 2; np++) {
                uint32_t t4[4];
                ldsm4(t4, sB[cur] + (uint32_t)(((wcol * 32 + np * 16 + fRow) * 40
                                                + k16 * 16 + fColH) * 2));
                bf[2*np][0] = t4[0]; bf[2*np][1] = t4[2];
                bf[2*np+1][0] = t4[1]; bf[2*np+1][1] = t4[3];
            }
            #pragma unroll
            for (int mt = 0; mt < 4; mt++)
                #pragma unroll
                for (int nt = 0; nt < 4; nt++)
                    mma_f16(c[mt][nt], af[mt], bf[nt][0], bf[nt][1]);
        }
        if (ks < 31) {
            #pragma unroll
            for (int i = 0; i < 4; i++) {
                int row = lrw + i * 32;
                int idx = row * 20 + (lc4 >> 1);
                *(uint2*)&Abuf[cur ^ 1][idx] = make_uint2(pack_f16(ra[i].x, ra[i].y),
                                                          pack_f16(ra[i].z, ra[i].w));
                *(uint2*)&Bbuf[cur ^ 1][idx] = make_uint2(pack_f16(rb[i].x, rb[i].y),
                                                          pack_f16(rb[i].z, rb[i].w));
            }
        }
        __syncthreads();
    }

    const int lrow = lane >> 2;
    const int lk   = lane & 3;
    #pragma unroll
    for (int mt = 0; mt < 4; mt++) {
        #pragma unroll
        for (int half = 0; half < 2; half++) {
            int row = bm + wrow * 64 + mt * 16 + lrow + half * 8;
            #pragma unroll
            for (int nt = 0; nt < 4; nt++) {
                int col = bn + wcol * 32 + nt * 8 + lk * 2;
                float v0 = c[mt][nt][half * 2];
                float v1 = c[mt][nt][half * 2 + 1];
                if (MODE == 0) {
                    int b = row >> 11, t = row & 2047;
                    int h = col >> 6, d = col & 63;
                    *(uint32_t*)&hdst[(((size_t)(b * Hc + h)) * Tc + t) * HDc + d] =
                        pack_f16((v0 + bias[col]) * scale, (v1 + bias[col + 1]) * scale);
                } else {
                    *(float2*)&Cout[(size_t)row * Ec + col] =
                        make_float2(v0 + bias[col], v1 + bias[col + 1]);
                }
            }
        }
    }
}

// ---------------------------------------------------------------------------
// attn_fused (all-fp16): per (bh, 64-row t-tile). Flash online softmax.
// No score materialization — writes only g_o and g_c.
// ---------------------------------------------------------------------------
__global__ void __launch_bounds__(128, 4) attn_fused(
    const unsigned char* __restrict__ am, const unsigned char* __restrict__ kpm)
{
    __shared__ uint32_t Ks[64 * 36];
    __shared__ uint32_t Vs[64 * 36];

    const int tid  = threadIdx.x;
    const int w    = tid >> 5;
    const int lane = tid & 31;
    const int lrow = lane >> 2;
    const int lk   = lane & 3;
    const int tbase = blockIdx.x * 64;
    const int bh = blockIdx.y;
    const int b = bh >> 4, h = bh & 15;

    const __half* Q  = g_q + (size_t)bh * Tc * HDc;
    const __half* Kg = g_k + (size_t)bh * Sc * HDc;
    const __half* Vg = g_v + (size_t)bh * Sc * HDc;

    const uint32_t sK = smem_u32(Ks);
    const uint32_t sV = smem_u32(Vs);

    const int fRow  = (lane & 7) + ((lane >> 3) & 1) * 8;
    const int fColH = (lane >> 4) * 8;

    #pragma unroll
    for (int i = 0; i < 4; i++) {
        int flat = tid + i * 128;
        int row = flat >> 3, c8 = (flat & 7) * 8;
        *(uint4*)((char*)Ks + row * 144 + c8 * 2) =
            *(const uint4*)(Q + (size_t)(tbase + row) * HDc + c8);
    }
    __syncthreads();
    uint32_t aQ[4][4];
    #pragma unroll
    for (int ks = 0; ks < 4; ks++)
        ldsm4(aQ[ks], sK + (uint32_t)((w * 16 + fRow) * 144 + (ks * 16 + fColH) * 2));
    __syncthreads();

    float Oa[8][4];
    #pragma unroll
    for (int i = 0; i < 8; i++)
        #pragma unroll
        for (int u = 0; u < 4; u++) Oa[i][u] = 0.f;
    float m_lo = -1e30f, m_hi = -1e30f, s_lo = 0.f, s_hi = 0.f;

    const int t_lo = tbase + w * 16 + lrow;
    const int t_hi = t_lo + 8;

    for (int s0 = 0; s0 < Sc; s0 += 64) {
        #pragma unroll
        for (int i = 0; i < 4; i++) {
            int flat = tid + i * 128;
            int row = flat >> 3, c8 = (flat & 7) * 8;
            *(uint4*)((char*)Ks + row * 144 + c8 * 2) =
                *(const uint4*)(Kg + (size_t)(s0 + row) * HDc + c8);
            *(uint4*)((char*)Vs + row * 144 + c8 * 2) =
                *(const uint4*)(Vg + (size_t)(s0 + row) * HDc + c8);
        }
        __syncthreads();

        float S[8][4];
        #pragma unroll
        for (int nt = 0; nt < 8; nt++)
            #pragma unroll
            for (int u = 0; u < 4; u++) S[nt][u] = 0.f;
        #pragma unroll
        for (int ks = 0; ks < 4; ks++) {
            #pragma unroll
            for (int np = 0; np < 4; np++) {
                uint32_t t4[4];
                ldsm4(t4, sK + (uint32_t)((np * 16 + fRow) * 144 + (ks * 16 + fColH) * 2));
                mma_f16(S[2*np],     aQ[ks], t4[0], t4[2]);
                mma_f16(S[2*np + 1], aQ[ks], t4[1], t4[3]);
            }
        }

        float tmax_lo = -1e30f, tmax_hi = -1e30f;
        #pragma unroll
        for (int nt = 0; nt < 8; nt++) {
            int col = s0 + nt * 8 + lk * 2;
            uchar2 a0 = *(const uchar2*)&am[(size_t)t_lo * Sc + col];
            uchar2 a1 = *(const uchar2*)&am[(size_t)t_hi * Sc + col];
            uchar2 kp = *(const uchar2*)&kpm[(size_t)b * Sc + col];
            if (a0.x | kp.x) S[nt][0] = 1e-10f;
            if (a0.y | kp.y) S[nt][1] = 1e-10f;
            if (a1.x | kp.x) S[nt][2] = 1e-10f;
            if (a1.y | kp.y) S[nt][3] = 1e-10f;
            tmax_lo = fmaxf(tmax_lo, fmaxf(S[nt][0], S[nt][1]));
            tmax_hi = fmaxf(tmax_hi, fmaxf(S[nt][2], S[nt][3]));
        }
        tmax_lo = fmaxf(tmax_lo, __shfl_xor_sync(0xffffffffu, tmax_lo, 1));
        tmax_lo = fmaxf(tmax_lo, __shfl_xor_sync(0xffffffffu, tmax_lo, 2));
        tmax_hi = fmaxf(tmax_hi, __shfl_xor_sync(0xffffffffu, tmax_hi, 1));
        tmax_hi = fmaxf(tmax_hi, __shfl_xor_sync(0xffffffffu, tmax_hi, 2));

        float mnew_lo = fmaxf(m_lo, tmax_lo);
        float mnew_hi = fmaxf(m_hi, tmax_hi);
        float f_lo = __expf(m_lo - mnew_lo);
        float f_hi = __expf(m_hi - mnew_hi);
        m_lo = mnew_lo; m_hi = mnew_hi;
        s_lo *= f_lo;   s_hi *= f_hi;
        #pragma unroll
        for (int nd = 0; nd < 8; nd++) {
            Oa[nd][0] *= f_lo; Oa[nd][1] *= f_lo;
            Oa[nd][2] *= f_hi; Oa[nd][3] *= f_hi;
        }

        uint32_t aP[4][4];
        #pragma unroll
        for (int nt = 0; nt < 8; nt++) {
            float p0 = __expf(S[nt][0] - m_lo);
            float p1 = __expf(S[nt][1] - m_lo);
            float p2 = __expf(S[nt][2] - m_hi);
            float p3 = __expf(S[nt][3] - m_hi);
            s_lo += p0 + p1;
            s_hi += p2 + p3;
            int kk = nt >> 1, hi = (nt & 1) * 2;
            aP[kk][hi]     = pack_f16(p0, p1);
            aP[kk][hi + 1] = pack_f16(p2, p3);
        }

        #pragma unroll
        for (int kk = 0; kk < 4; kk++) {
            int vrow = kk * 16 + fRow;
            #pragma unroll
            for (int nd16 = 0; nd16 < 4; nd16++) {
                uint32_t t4[4];
                int vcol = nd16 * 16 + (lane >> 4) * 8;
                ldsm4t(t4, sV + (uint32_t)(vrow * 144 + vcol * 2));
                mma_f16(Oa[nd16 * 2],     aP[kk], t4[0], t4[1]);
                mma_f16(Oa[nd16 * 2 + 1], aP[kk], t4[2], t4[3]);
            }
        }
        __syncthreads();
    }

    float r_lo = s_lo, r_hi = s_hi;
    r_lo += __shfl_xor_sync(0xffffffffu, r_lo, 1);
    r_lo += __shfl_xor_sync(0xffffffffu, r_lo, 2);
    r_hi += __shfl_xor_sync(0xffffffffu, r_hi, 1);
    r_hi += __shfl_xor_sync(0xffffffffu, r_hi, 2);
    const float inv_lo = 1.0f / r_lo;
    const float inv_hi = 1.0f / r_hi;

    #pragma unroll
    for (int nd = 0; nd < 8; nd++) {
        int d = nd * 8 + lk * 2;
        *(float2*)&g_o[(((size_t)b * Tc + t_lo) * Hc + h) * HDc + d] =
            make_float2(Oa[nd][0] * inv_lo, Oa[nd][1] * inv_lo);
        *(float2*)&g_o[(((size_t)b * Tc + t_hi) * Hc + h) * HDc + d] =
            make_float2(Oa[nd][2] * inv_hi, Oa[nd][3] * inv_hi);
    }
    if (lk == 0) {
        g_c[(size_t)bh * Tc + t_lo] = m_lo + __logf(r_lo);
        g_c[(size_t)bh * Tc + t_hi] = m_hi + __logf(r_hi);
    }
}

// ---------------------------------------------------------------------------
// headmax_gemm: per (b, 64x64 t x s tile). Recomputes S_h for all 16 heads
// (bit-identical fp16 mma vs attn_fused) and writes
//   attn_max[b,t,s] = exp(max_h (S_h - c[b,h,t])).
// ---------------------------------------------------------------------------
__global__ void __launch_bounds__(128, 4) headmax_gemm(
    const unsigned char* __restrict__ am, const unsigned char* __restrict__ kpm,
    float* __restrict__ out2)
{
    __shared__ uint32_t Qs[64 * 36];
    __shared__ uint32_t Ks[64 * 36];

    const int tid  = threadIdx.x;
    const int w    = tid >> 5;
    const int lane = tid & 31;
    const int lrow = lane >> 2;
    const int lk   = lane & 3;
    const int b  = blockIdx.z;
    const int tb = blockIdx.y * 64;
    const int sb = blockIdx.x * 64;

    const uint32_t sQ = smem_u32(Qs);
    const uint32_t sKb = smem_u32(Ks);

    const int fRow  = (lane & 7) + ((lane >> 3) & 1) * 8;
    const int fColH = (lane >> 4) * 8;

    const int t_lo = tb + w * 16 + lrow;
    const int t_hi = t_lo + 8;

    // precompute per-thread mask bits (bit nt*4+u)
    uint32_t mbits = 0;
    #pragma unroll
    for (int nt = 0; nt < 8; nt++) {
        int col = sb + nt * 8 + lk * 2;
        uchar2 a0 = *(const uchar2*)&am[(size_t)t_lo * Sc + col];
        uchar2 a1 = *(const uchar2*)&am[(size_t)t_hi * Sc + col];
        uchar2 kp = *(const uchar2*)&kpm[(size_t)b * Sc + col];
        if (a0.x | kp.x) mbits |= 1u << (nt * 4 + 0);
        if (a0.y | kp.y) mbits |= 1u << (nt * 4 + 1);
        if (a1.x | kp.x) mbits |= 1u << (nt * 4 + 2);
        if (a1.y | kp.y) mbits |= 1u << (nt * 4 + 3);
    }

    float best[8][4];
    #pragma unroll
    for (int nt = 0; nt < 8; nt++)
        #pragma unroll
        for (int u = 0; u < 4; u++) best[nt][u] = -1e30f;

    for (int h = 0; h < Hc; h++) {
        const int bh = b * Hc + h;
        const __half* Q  = g_q + (size_t)bh * Tc * HDc;
        const __half* Kg = g_k + (size_t)bh * Sc * HDc;

        #pragma unroll
        for (int i = 0; i < 4; i++) {
            int flat = tid + i * 128;
            int row = flat >> 3, c8 = (flat & 7) * 8;
            *(uint4*)((char*)Qs + row * 144 + c8 * 2) =
                *(const uint4*)(Q + (size_t)(tb + row) * HDc + c8);
            *(uint4*)((char*)Ks + row * 144 + c8 * 2) =
                *(const uint4*)(Kg + (size_t)(sb + row) * HDc + c8);
        }
        __syncthreads();

        uint32_t aQ[4][4];
        #pragma unroll
        for (int ks = 0; ks < 4; ks++)
            ldsm4(aQ[ks], sQ + (uint32_t)((w * 16 + fRow) * 144 + (ks * 16 + fColH) * 2));

        float S[8][4];
        #pragma unroll
        for (int nt = 0; nt < 8; nt++)
            #pragma unroll
            for (int u = 0; u < 4; u++) S[nt][u] = 0.f;
        #pragma unroll
        for (int ks = 0; ks < 4; ks++) {
            #pragma unroll
            for (int np = 0; np < 4; np++) {
                uint32_t t4[4];
                ldsm4(t4, sKb + (uint32_t)((np * 16 + fRow) * 144 + (ks * 16 + fColH) * 2));
                mma_f16(S[2*np],     aQ[ks], t4[0], t4[2]);
                mma_f16(S[2*np + 1], aQ[ks], t4[1], t4[3]);
            }
        }

        const float c_lo = g_c[(size_t)bh * Tc + t_lo];
        const float c_hi = g_c[(size_t)bh * Tc + t_hi];
        #pragma unroll
        for (int nt = 0; nt < 8; nt++) {
            float v0 = (mbits >> (nt * 4 + 0)) & 1 ? 1e-10f : S[nt][0];
            float v1 = (mbits >> (nt * 4 + 1)) & 1 ? 1e-10f : S[nt][1];
            float v2 = (mbits >> (nt * 4 + 2)) & 1 ? 1e-10f : S[nt][2];
            float v3 = (mbits >> (nt * 4 + 3)) & 1 ? 1e-10f : S[nt][3];
            best[nt][0] = fmaxf(best[nt][0], v0 - c_lo);
            best[nt][1] = fmaxf(best[nt][1], v1 - c_lo);
            best[nt][2] = fmaxf(best[nt][2], v2 - c_hi);
            best[nt][3] = fmaxf(best[nt][3], v3 - c_hi);
        }
        __syncthreads();
    }

    #pragma unroll
    for (int nt = 0; nt < 8; nt++) {
        int col = sb + nt * 8 + lk * 2;
        *(float2*)&out2[((size_t)b * Tc + t_lo) * Sc + col] =
            make_float2(__expf(best[nt][0]), __expf(best[nt][1]));
        *(float2*)&out2[((size_t)b * Tc + t_hi) * Sc + col] =
            make_float2(__expf(best[nt][2]), __expf(best[nt][3]));
    }
}

// ---------------------------------------------------------------------------
extern "C" void kernel_launch(void* const* d_in, const int* in_sizes, int n_in,
                              void* d_out, int out_size)
{
    const float* query = (const float*)d_in[0];
    const float* key   = (const float*)d_in[1];
    const float* value = (const float*)d_in[2];
    const unsigned char* kpm = (const unsigned char*)d_in[3];
    const unsigned char* am  = (const unsigned char*)d_in[4];
    const float* Wq = (const float*)d_in[5];
    const float* bq = (const float*)d_in[6];
    const float* Wk = (const float*)d_in[7];
    const float* bk = (const float*)d_in[8];
    const float* Wv = (const float*)d_in[9];
    const float* bv = (const float*)d_in[10];
    const float* Wo = (const float*)d_in[11];
    const float* bo = (const float*)d_in[12];

    float* out      = (float*)d_out;
    float* attn_max = (float*)d_out + (size_t)Bc * Tc * Ec;

    float *po;
    cudaGetSymbolAddress((void**)&po, g_o);

    static cudaStream_t s2 = nullptr;
    static cudaEvent_t evFork = nullptr, evJoin = nullptr;
    if (s2 == nullptr) {
        cudaStreamCreateWithFlags(&s2, cudaStreamNonBlocking);
        cudaEventCreateWithFlags(&evFork, cudaEventDisableTiming);
        cudaEventCreateWithFlags(&evJoin, cudaEventDisableTiming);
    }

    const int GEMM_SMEM = 4 * 2560 * 4;   // 40960 B (fp16 double buffer)
    cudaFuncSetAttribute(gemm_db<0>, cudaFuncAttributeMaxDynamicSharedMemorySize, GEMM_SMEM);
    cudaFuncSetAttribute(gemm_db<3>, cudaFuncAttributeMaxDynamicSharedMemorySize, GEMM_SMEM);

    dim3 thr(256);

    // Batched Q/K/V projections -> fp16 (grid.z = 0,1,2)
    gemm_db<0><<<dim3(Ec / 128, (Bc * Tc) / 128, 3), thr, GEMM_SMEM>>>(
        query, key, value, Wq, Wk, Wv, bq, bk, bv, nullptr);

    // Fused score + online softmax + P@V  (writes g_o, g_c only)
    attn_fused<<<dim3(Tc / 64, Bc * Hc), dim3(128)>>>(am, kpm);

    // fork: attn_max recompute on side stream, out-projection on main stream
    cudaEventRecord(evFork, 0);
    cudaStreamWaitEvent(s2, evFork, 0);

    headmax_gemm<<<dim3(Sc / 64, Tc / 64, Bc), dim3(128), 0, s2>>>(am, kpm, attn_max);

    gemm_db<3><<<dim3(Ec / 128, (Bc * Tc) / 128, 1), thr, GEMM_SMEM>>>(
        po, nullptr, nullptr, Wo, nullptr, nullptr, bo, nullptr, nullptr, out);

    cudaEventRecord(evJoin, s2);
    cudaStreamWaitEvent(0, evJoin, 0);
}